// round 1
// baseline (speedup 1.0000x reference)
#include <cuda_runtime.h>
#include <math.h>

// Problem constants (with headroom on N/E for safety)
#define FIN   500
#define FH    128
#define FOUT  47
#define NMAX  65536
#define EMAX  1048576

// ---------------- scratch (static device globals; no allocation) -------------
__device__ float g_dinv[NMAX];
__device__ int   g_cnt[NMAX];
__device__ int   g_rowptr[NMAX + 1];
__device__ int   g_wp[NMAX];
__device__ int   g_col[EMAX];
__device__ float g_H1 [(size_t)NMAX * FH];   // x @ W1
__device__ float g_H1r[(size_t)NMAX * FH];   // relu(agg1 + b1)
__device__ float g_H2 [(size_t)NMAX * FOUT]; // H1r @ W2
__device__ int   g_is64;

// Read edge endpoint idx from buffer that is either int32 or int64 (LE, values < 2^31)
__device__ __forceinline__ int ld_edge(const int* p, long long idx, int is64) {
    return is64 ? p[2 * idx] : p[idx];
}

// ---------------- dtype detection -------------------------------------------
// int64 little-endian: odd 32-bit words are 0 (values in [0, 50000)).
// int32: odd words are random node ids; P(all 32 probes == 0) ~ (1/50000)^32.
__global__ void k_detect(const int* ei) {
    int lane = threadIdx.x;
    int nz = 0;
#pragma unroll
    for (int u = 0; u < 1; u++) {
        if (ei[2 * lane + 1] != 0) nz = 1;
    }
    unsigned b = __ballot_sync(0xffffffffu, nz);
    if (lane == 0) g_is64 = (b == 0u) ? 1 : 0;
}

__global__ void k_zero_cnt(int n) {
    int i = blockIdx.x * blockDim.x + threadIdx.x;
    if (i < n) g_cnt[i] = 0;
}

__global__ void k_degree(const int* ei, long long E) {
    long long e = (long long)blockIdx.x * blockDim.x + threadIdx.x;
    if (e >= E) return;
    int is64 = g_is64;
    int dst = ld_edge(ei, E + e, is64);
    atomicAdd(&g_cnt[dst], 1);
}

// single-block exclusive scan of counts -> rowptr; also dinv = rsqrt(indeg+1), wp init
__global__ void k_scan(int n) {
    __shared__ int tsum[1024];
    int t = threadIdx.x;
    int per = (n + 1023) / 1024;
    int start = t * per;
    int end = start + per; if (end > n) end = n;
    int s = 0;
    for (int i = start; i < end; i++) s += g_cnt[i];
    tsum[t] = s;
    __syncthreads();
    for (int off = 1; off < 1024; off <<= 1) {
        int v = (t >= off) ? tsum[t - off] : 0;
        __syncthreads();
        tsum[t] += v;
        __syncthreads();
    }
    int run = tsum[t] - s;  // exclusive prefix for this chunk
    for (int i = start; i < end; i++) {
        g_rowptr[i] = run;
        g_wp[i] = run;
        g_dinv[i] = rsqrtf((float)(g_cnt[i] + 1));  // +1 self-loop
        run += g_cnt[i];
    }
    if (t == 1023) g_rowptr[n] = tsum[1023];
}

__global__ void k_scatter(const int* ei, long long E) {
    long long e = (long long)blockIdx.x * blockDim.x + threadIdx.x;
    if (e >= E) return;
    int is64 = g_is64;
    int src = ld_edge(ei, e, is64);
    int dst = ld_edge(ei, E + e, is64);
    int pos = atomicAdd(&g_wp[dst], 1);
    g_col[pos] = src;
}

// ---------------- GEMM1: H1 = x @ W1  (n x 500) @ (500 x 128) ---------------
// 64x128 tile per block, 256 threads, each thread 4x8 outputs, BK=16.
__global__ __launch_bounds__(256) void k_gemm1(
    const float* __restrict__ x, const float* __restrict__ W, int n)
{
    __shared__ __align__(16) float As[16][68];   // [k][m], padded
    __shared__ __align__(16) float Bs[16][FH];   // [k][n]

    int tid = threadIdx.x;
    int row0 = blockIdx.x * 64;
    int tr = tid >> 4;   // 0..15
    int tc = tid & 15;   // 0..15

    float acc[4][8];
#pragma unroll
    for (int i = 0; i < 4; i++)
#pragma unroll
        for (int j = 0; j < 8; j++) acc[i][j] = 0.f;

    for (int k0 = 0; k0 < FIN; k0 += 16) {
        // load A tile: 64 rows x 16 k
        int lrow = tid >> 2;
        int kbase = (tid & 3) << 2;
#pragma unroll
        for (int u = 0; u < 4; u++) {
            int kk = kbase + u;
            int gr = row0 + lrow, gk = k0 + kk;
            float v = (gr < n && gk < FIN) ? x[(size_t)gr * FIN + gk] : 0.f;
            As[kk][lrow] = v;
        }
        // load B tile: 16 k x 128 cols
#pragma unroll
        for (int u = 0; u < 8; u++) {
            int idx = tid + u * 256;
            int bk = idx >> 7, bc = idx & 127;
            int gk = k0 + bk;
            Bs[bk][bc] = (gk < FIN) ? W[(size_t)gk * FH + bc] : 0.f;
        }
        __syncthreads();

#pragma unroll
        for (int kk = 0; kk < 16; kk++) {
            float4 av  = *reinterpret_cast<const float4*>(&As[kk][tr * 4]);
            float4 bv0 = *reinterpret_cast<const float4*>(&Bs[kk][tc * 8]);
            float4 bv1 = *reinterpret_cast<const float4*>(&Bs[kk][tc * 8 + 4]);
            float a[4] = {av.x, av.y, av.z, av.w};
            float b[8] = {bv0.x, bv0.y, bv0.z, bv0.w, bv1.x, bv1.y, bv1.z, bv1.w};
#pragma unroll
            for (int i = 0; i < 4; i++)
#pragma unroll
                for (int j = 0; j < 8; j++) acc[i][j] += a[i] * b[j];
        }
        __syncthreads();
    }

#pragma unroll
    for (int i = 0; i < 4; i++) {
        int gr = row0 + tr * 4 + i;
        if (gr < n) {
#pragma unroll
            for (int j = 0; j < 8; j++)
                g_H1[(size_t)gr * FH + tc * 8 + j] = acc[i][j];
        }
    }
}

// ---------------- agg1: H1r = relu( Ahat @ H1 + b1 ) ------------------------
// One block (128 threads) per node; feature t per thread. Edge lists staged in smem.
__global__ __launch_bounds__(128) void k_agg1(const float* __restrict__ b1, int n) {
    __shared__ int   ss[64];
    __shared__ float ws[64];
    int i = blockIdx.x;
    int t = threadIdx.x;
    float di = g_dinv[i];
    float acc = g_H1[(size_t)i * FH + t] * di * di;   // self loop
    int beg = g_rowptr[i], end = g_rowptr[i + 1];
    for (int base = beg; base < end; base += 64) {
        int c = end - base; if (c > 64) c = 64;
        if (t < c) {
            int s = g_col[base + t];
            ss[t] = s;
            ws[t] = g_dinv[s] * di;
        }
        __syncthreads();
        int j = 0;
        for (; j + 3 < c; j += 4) {
            int s0 = ss[j], s1 = ss[j+1], s2 = ss[j+2], s3 = ss[j+3];
            float w0 = ws[j], w1 = ws[j+1], w2 = ws[j+2], w3 = ws[j+3];
            float h0 = g_H1[(size_t)s0 * FH + t];
            float h1 = g_H1[(size_t)s1 * FH + t];
            float h2 = g_H1[(size_t)s2 * FH + t];
            float h3 = g_H1[(size_t)s3 * FH + t];
            acc += h0 * w0; acc += h1 * w1; acc += h2 * w2; acc += h3 * w3;
        }
        for (; j < c; j++) acc += g_H1[(size_t)ss[j] * FH + t] * ws[j];
        __syncthreads();
    }
    acc += b1[t];
    g_H1r[(size_t)i * FH + t] = fmaxf(acc, 0.f);
}

// ---------------- GEMM2: H2 = H1r @ W2  (n x 128) @ (128 x 47) --------------
__global__ __launch_bounds__(256) void k_gemm2(const float* __restrict__ W2, int n) {
    __shared__ float Ws[FH * FOUT];   // 24KB
    __shared__ float Hs[16][FH];      // 8KB
    int tid = threadIdx.x;
    int row0 = blockIdx.x * 16;
    for (int idx = tid; idx < FH * FOUT; idx += 256) Ws[idx] = W2[idx];
    for (int idx = tid; idx < 16 * FH; idx += 256) {
        int r = idx >> 7, k = idx & 127;
        int gr = row0 + r;
        Hs[r][k] = (gr < n) ? g_H1r[(size_t)gr * FH + k] : 0.f;
    }
    __syncthreads();
    for (int o = tid; o < 16 * FOUT; o += 256) {
        int r = o / FOUT, c = o - r * FOUT;
        float acc = 0.f;
#pragma unroll 8
        for (int k = 0; k < FH; k++) acc += Hs[r][k] * Ws[k * FOUT + c];
        int gr = row0 + r;
        if (gr < n) g_H2[(size_t)gr * FOUT + c] = acc;
    }
}

// ---------------- agg2 + bias + log_softmax ---------------------------------
// One warp per node; lane covers feature lane and lane+32.
__global__ __launch_bounds__(256) void k_agg2(
    const float* __restrict__ b2, float* __restrict__ out, int n)
{
    int gw = (blockIdx.x * blockDim.x + threadIdx.x) >> 5;
    int lane = threadIdx.x & 31;
    if (gw >= n) return;
    int i = gw;
    float di = g_dinv[i];
    bool v0 = lane < FOUT;
    bool v1 = (lane + 32) < FOUT;
    float a0 = v0 ? g_H2[(size_t)i * FOUT + lane]      * di * di : 0.f;
    float a1 = v1 ? g_H2[(size_t)i * FOUT + lane + 32] * di * di : 0.f;

    int beg = g_rowptr[i], end = g_rowptr[i + 1];
    for (int base = beg; base < end; base += 32) {
        int c = end - base; if (c > 32) c = 32;
        int s = 0; float w = 0.f;
        if (lane < c) { s = g_col[base + lane]; w = g_dinv[s] * di; }
        for (int k = 0; k < c; k++) {
            int   sk = __shfl_sync(0xffffffffu, s, k);
            float wk = __shfl_sync(0xffffffffu, w, k);
            if (v0) a0 += g_H2[(size_t)sk * FOUT + lane]      * wk;
            if (v1) a1 += g_H2[(size_t)sk * FOUT + lane + 32] * wk;
        }
    }
    if (v0) a0 += b2[lane];
    if (v1) a1 += b2[lane + 32];

    float m = fmaxf(v0 ? a0 : -INFINITY, v1 ? a1 : -INFINITY);
#pragma unroll
    for (int off = 16; off; off >>= 1) m = fmaxf(m, __shfl_xor_sync(0xffffffffu, m, off));
    float e = (v0 ? expf(a0 - m) : 0.f) + (v1 ? expf(a1 - m) : 0.f);
#pragma unroll
    for (int off = 16; off; off >>= 1) e += __shfl_xor_sync(0xffffffffu, e, off);
    float ls = m + logf(e);
    if (v0) out[(size_t)i * FOUT + lane]      = a0 - ls;
    if (v1) out[(size_t)i * FOUT + lane + 32] = a1 - ls;
}

// ---------------- launch ----------------------------------------------------
extern "C" void kernel_launch(void* const* d_in, const int* in_sizes, int n_in,
                              void* d_out, int out_size)
{
    const float* x  = (const float*)d_in[0];
    const float* W1 = (const float*)d_in[1];
    const float* b1 = (const float*)d_in[2];
    const float* W2 = (const float*)d_in[3];
    const float* b2 = (const float*)d_in[4];
    const int*   ei = (const int*)d_in[5];   // int32 or int64; detected on device
    float* out = (float*)d_out;

    int n = in_sizes[0] / FIN;
    long long E = in_sizes[5] / 2;

    k_detect<<<1, 32>>>(ei);
    k_zero_cnt<<<(n + 255) / 256, 256>>>(n);
    k_degree<<<(int)((E + 255) / 256), 256>>>(ei, E);
    k_scan<<<1, 1024>>>(n);
    k_scatter<<<(int)((E + 255) / 256), 256>>>(ei, E);
    k_gemm1<<<(n + 63) / 64, 256>>>(x, W1, n);
    k_agg1<<<n, 128>>>(b1, n);
    k_gemm2<<<(n + 15) / 16, 256>>>(W2, n);
    k_agg2<<<(n * 32 + 255) / 256, 256>>>(b2, out, n);
}

// round 3
// speedup vs baseline: 1.6282x; 1.6282x over previous
#include <cuda_runtime.h>
#include <math.h>

// Problem constants (with headroom on N/E for safety)
#define FIN   500
#define FH    128
#define FOUT  47
#define NMAX  65536
#define EMAX  1048576

// ---------------- scratch (static device globals; no allocation) -------------
__device__ __align__(16) float g_dinv[NMAX];
__device__ int   g_cnt[NMAX];
__device__ int   g_rowptr[NMAX + 1];
__device__ int   g_wp[NMAX];
__device__ int   g_col[EMAX];
__device__ int   g_bsum[256];
__device__ int   g_boff[256];
__device__ __align__(16) float g_H1 [(size_t)NMAX * FH];   // x @ W1
__device__ __align__(16) float g_H1r[(size_t)NMAX * FH];   // relu(agg1 + b1)
__device__ __align__(16) float g_H2 [(size_t)NMAX * FOUT]; // H1r @ W2
__device__ int   g_is64;

__device__ __forceinline__ int ld_edge(const int* p, long long idx, int is64) {
    return is64 ? p[2 * idx] : p[idx];
}

// ---------------- dtype detection -------------------------------------------
// int64 LE: odd 32-bit words are 0 (values < 50000). int32: odd words random.
__global__ void k_detect(const int* ei) {
    int lane = threadIdx.x;
    int nz = (ei[2 * lane + 1] != 0) ? 1 : 0;
    unsigned b = __ballot_sync(0xffffffffu, nz);
    if (lane == 0) g_is64 = (b == 0u) ? 1 : 0;
}

__global__ void k_zero_cnt(int n) {
    int i = blockIdx.x * blockDim.x + threadIdx.x;
    if (i < n) g_cnt[i] = 0;
}

__global__ void k_degree(const int* ei, long long E) {
    long long e = (long long)blockIdx.x * blockDim.x + threadIdx.x;
    if (e >= E) return;
    int is64 = g_is64;
    int dst = ld_edge(ei, E + e, is64);
    atomicAdd(&g_cnt[dst], 1);
}

// ---------------- 3-phase parallel scan --------------------------------------
// phase 1: per-block (256 elems) reduction -> g_bsum
__global__ void k_part(int n) {
    __shared__ int sh[8];
    int t = threadIdx.x;
    int i = blockIdx.x * 256 + t;
    int v = (i < n) ? g_cnt[i] : 0;
#pragma unroll
    for (int off = 16; off; off >>= 1) v += __shfl_xor_sync(0xffffffffu, v, off);
    if ((t & 31) == 0) sh[t >> 5] = v;
    __syncthreads();
    if (t < 8) {
        int s = sh[t];
#pragma unroll
        for (int off = 4; off; off >>= 1) s += __shfl_xor_sync(0xffu, s, off);
        if (t == 0) g_bsum[blockIdx.x] = s;
    }
}

// phase 2: single block scans up to 256 partials -> g_boff (exclusive), total
__global__ void k_scan2(int n, int nb) {
    __shared__ int sh[256];
    int t = threadIdx.x;
    int v = (t < nb) ? g_bsum[t] : 0;
    sh[t] = v;
    __syncthreads();
#pragma unroll
    for (int off = 1; off < 256; off <<= 1) {
        int u = (t >= off) ? sh[t - off] : 0;
        __syncthreads();
        sh[t] += u;
        __syncthreads();
    }
    g_boff[t] = sh[t] - v;   // exclusive
    if (t == 255) g_rowptr[n] = sh[255];
}

// phase 3: per-block internal scan + write rowptr/wp/dinv
__global__ void k_write(int n) {
    __shared__ int sh[256];
    int t = threadIdx.x;
    int i = blockIdx.x * 256 + t;
    int c = (i < n) ? g_cnt[i] : 0;
    sh[t] = c;
    __syncthreads();
#pragma unroll
    for (int off = 1; off < 256; off <<= 1) {
        int u = (t >= off) ? sh[t - off] : 0;
        __syncthreads();
        sh[t] += u;
        __syncthreads();
    }
    if (i < n) {
        int pos = g_boff[blockIdx.x] + sh[t] - c;
        g_rowptr[i] = pos;
        g_wp[i] = pos;
        g_dinv[i] = rsqrtf((float)(c + 1));   // +1 self-loop
    }
}

__global__ void k_scatter(const int* ei, long long E) {
    long long e = (long long)blockIdx.x * blockDim.x + threadIdx.x;
    if (e >= E) return;
    int is64 = g_is64;
    int src = ld_edge(ei, e, is64);
    int dst = ld_edge(ei, E + e, is64);
    int pos = atomicAdd(&g_wp[dst], 1);
    g_col[pos] = src;
}

// ---------------- GEMM1: H1 = x @ W1  (n x 500) @ (500 x 128) ---------------
// 128x128 tile, BK=16, double-buffered, 256 threads, 8x8 micro-tile.
#define G1_KT 32   // ceil(500/16)
__global__ __launch_bounds__(256, 2) void k_gemm1(
    const float* __restrict__ x, const float* __restrict__ W, int n)
{
    __shared__ __align__(16) float As[2][16][132];
    __shared__ __align__(16) float Bs[2][16][128];

    int tid = threadIdx.x;
    int row0 = blockIdx.x * 128;
    int tr = tid >> 4;   // 0..15 -> rows tr*8
    int tc = tid & 15;   // 0..15 -> cols tc*8

    float acc[8][8];
#pragma unroll
    for (int i = 0; i < 8; i++)
#pragma unroll
        for (int j = 0; j < 8; j++) acc[i][j] = 0.f;

    float4 a_ld[2], b_ld[2];
    // loader mapping (per u in 0..1): f4 = tid + u*256
    //   A: a_row = f4>>2 (0..127), grp = f4&3 (k sub-group of 4)
    //   B: bk = f4>>5 (0..15),     bc4 = f4&31

#define G1_LOAD(k0)                                                            \
    {                                                                          \
        _Pragma("unroll")                                                      \
        for (int u = 0; u < 2; u++) {                                          \
            int f4 = tid + u * 256;                                            \
            int a_row = f4 >> 2, grp = f4 & 3;                                 \
            int gk = (k0) + grp * 4;                                           \
            int gr = row0 + a_row;                                             \
            if (gr < n && gk + 4 <= FIN)                                       \
                a_ld[u] = *reinterpret_cast<const float4*>(&x[(size_t)gr * FIN + gk]); \
            else a_ld[u] = make_float4(0.f, 0.f, 0.f, 0.f);                    \
            int bk = f4 >> 5, bc4 = f4 & 31;                                   \
            int gkb = (k0) + bk;                                               \
            if (gkb < FIN)                                                     \
                b_ld[u] = *reinterpret_cast<const float4*>(&W[(size_t)gkb * FH + bc4 * 4]); \
            else b_ld[u] = make_float4(0.f, 0.f, 0.f, 0.f);                    \
        }                                                                      \
    }

#define G1_STORE(buf)                                                          \
    {                                                                          \
        _Pragma("unroll")                                                      \
        for (int u = 0; u < 2; u++) {                                          \
            int f4 = tid + u * 256;                                            \
            int a_row = f4 >> 2, grp = f4 & 3;                                 \
            As[buf][grp * 4 + 0][a_row] = a_ld[u].x;                           \
            As[buf][grp * 4 + 1][a_row] = a_ld[u].y;                           \
            As[buf][grp * 4 + 2][a_row] = a_ld[u].z;                           \
            As[buf][grp * 4 + 3][a_row] = a_ld[u].w;                           \
            int bk = f4 >> 5, bc4 = f4 & 31;                                   \
            *reinterpret_cast<float4*>(&Bs[buf][bk][bc4 * 4]) = b_ld[u];       \
        }                                                                      \
    }

    G1_LOAD(0)
    G1_STORE(0)
    __syncthreads();

    for (int kt = 0; kt < G1_KT; kt++) {
        int cbuf = kt & 1;
        if (kt + 1 < G1_KT) G1_LOAD((kt + 1) * 16)
#pragma unroll
        for (int kk = 0; kk < 16; kk++) {
            float4 a0 = *reinterpret_cast<const float4*>(&As[cbuf][kk][tr * 8]);
            float4 a1 = *reinterpret_cast<const float4*>(&As[cbuf][kk][tr * 8 + 4]);
            float4 b0 = *reinterpret_cast<const float4*>(&Bs[cbuf][kk][tc * 8]);
            float4 b1 = *reinterpret_cast<const float4*>(&Bs[cbuf][kk][tc * 8 + 4]);
            float a[8] = {a0.x, a0.y, a0.z, a0.w, a1.x, a1.y, a1.z, a1.w};
            float b[8] = {b0.x, b0.y, b0.z, b0.w, b1.x, b1.y, b1.z, b1.w};
#pragma unroll
            for (int i = 0; i < 8; i++)
#pragma unroll
                for (int j = 0; j < 8; j++) acc[i][j] += a[i] * b[j];
        }
        if (kt + 1 < G1_KT) G1_STORE(cbuf ^ 1)
        __syncthreads();
    }

#pragma unroll
    for (int i = 0; i < 8; i++) {
        int gr = row0 + tr * 8 + i;
        if (gr < n) {
            float4 o0 = make_float4(acc[i][0], acc[i][1], acc[i][2], acc[i][3]);
            float4 o1 = make_float4(acc[i][4], acc[i][5], acc[i][6], acc[i][7]);
            *reinterpret_cast<float4*>(&g_H1[(size_t)gr * FH + tc * 8])     = o0;
            *reinterpret_cast<float4*>(&g_H1[(size_t)gr * FH + tc * 8 + 4]) = o1;
        }
    }
#undef G1_LOAD
#undef G1_STORE
}

// ---------------- agg1: H1r = relu( Ahat @ H1 + b1 ) ------------------------
// One warp per node; lane covers a float4 (4 features). Coalesced 512B gathers.
__global__ __launch_bounds__(256) void k_agg1(const float* __restrict__ b1, int n) {
    int gw = (blockIdx.x * blockDim.x + threadIdx.x) >> 5;
    int lane = threadIdx.x & 31;
    if (gw >= n) return;
    int i = gw;
    float di = g_dinv[i];
    const float4* H = reinterpret_cast<const float4*>(g_H1);
    float4 h = H[(size_t)i * 32 + lane];
    float sw = di * di;
    float4 acc = make_float4(h.x * sw, h.y * sw, h.z * sw, h.w * sw);

    int beg = g_rowptr[i], end = g_rowptr[i + 1];
    for (int base = beg; base < end; base += 32) {
        int c = end - base; if (c > 32) c = 32;
        int s = 0; float w = 0.f;
        if (lane < c) { s = g_col[base + lane]; w = g_dinv[s] * di; }
        int k = 0;
        for (; k + 4 <= c; k += 4) {
            int   s0 = __shfl_sync(0xffffffffu, s, k);
            int   s1 = __shfl_sync(0xffffffffu, s, k + 1);
            int   s2 = __shfl_sync(0xffffffffu, s, k + 2);
            int   s3 = __shfl_sync(0xffffffffu, s, k + 3);
            float w0 = __shfl_sync(0xffffffffu, w, k);
            float w1 = __shfl_sync(0xffffffffu, w, k + 1);
            float w2 = __shfl_sync(0xffffffffu, w, k + 2);
            float w3 = __shfl_sync(0xffffffffu, w, k + 3);
            float4 v0 = H[(size_t)s0 * 32 + lane];
            float4 v1 = H[(size_t)s1 * 32 + lane];
            float4 v2 = H[(size_t)s2 * 32 + lane];
            float4 v3 = H[(size_t)s3 * 32 + lane];
            acc.x += v0.x * w0; acc.y += v0.y * w0; acc.z += v0.z * w0; acc.w += v0.w * w0;
            acc.x += v1.x * w1; acc.y += v1.y * w1; acc.z += v1.z * w1; acc.w += v1.w * w1;
            acc.x += v2.x * w2; acc.y += v2.y * w2; acc.z += v2.z * w2; acc.w += v2.w * w2;
            acc.x += v3.x * w3; acc.y += v3.y * w3; acc.z += v3.z * w3; acc.w += v3.w * w3;
        }
        for (; k < c; k++) {
            int   sk = __shfl_sync(0xffffffffu, s, k);
            float wk = __shfl_sync(0xffffffffu, w, k);
            float4 v = H[(size_t)sk * 32 + lane];
            acc.x += v.x * wk; acc.y += v.y * wk; acc.z += v.z * wk; acc.w += v.w * wk;
        }
    }
    float4 b = reinterpret_cast<const float4*>(b1)[lane];
    float4 o = make_float4(fmaxf(acc.x + b.x, 0.f), fmaxf(acc.y + b.y, 0.f),
                           fmaxf(acc.z + b.z, 0.f), fmaxf(acc.w + b.w, 0.f));
    reinterpret_cast<float4*>(g_H1r)[(size_t)i * 32 + lane] = o;
}

// ---------------- GEMM2: H2 = H1r @ W2  (n x 128) @ (128 x 47) --------------
// 128x48(pad) tile, BK=16, double-buffered, 128 threads, 8x6 micro-tile.
__global__ __launch_bounds__(128, 4) void k_gemm2(const float* __restrict__ W2, int n) {
    __shared__ __align__(16) float As[2][16][132];
    __shared__ __align__(16) float Bs[2][16][48];

    int tid = threadIdx.x;
    int row0 = blockIdx.x * 128;
    int tr = tid >> 3;  // 0..15 -> rows tr*8
    int tc = tid & 7;   // 0..7  -> cols tc*6

    float acc[8][6];
#pragma unroll
    for (int i = 0; i < 8; i++)
#pragma unroll
        for (int j = 0; j < 6; j++) acc[i][j] = 0.f;

    float4 a_ld[4];
    float  b_ld[6];

#define G2_LOAD(k0)                                                            \
    {                                                                          \
        _Pragma("unroll")                                                      \
        for (int u = 0; u < 4; u++) {                                          \
            int f4 = tid + u * 128;                                            \
            int a_row = f4 >> 2, grp = f4 & 3;                                 \
            int gr = row0 + a_row;                                             \
            a_ld[u] = (gr < n)                                                 \
                ? *reinterpret_cast<const float4*>(&g_H1r[(size_t)gr * FH + (k0) + grp * 4]) \
                : make_float4(0.f, 0.f, 0.f, 0.f);                             \
        }                                                                      \
        _Pragma("unroll")                                                      \
        for (int u = 0; u < 6; u++) {                                          \
            int idx = tid + u * 128;                                           \
            int bk = idx / 48, bc = idx - bk * 48;                             \
            b_ld[u] = (bc < FOUT) ? W2[(size_t)((k0) + bk) * FOUT + bc] : 0.f; \
        }                                                                      \
    }

#define G2_STORE(buf)                                                          \
    {                                                                          \
        _Pragma("unroll")                                                      \
        for (int u = 0; u < 4; u++) {                                          \
            int f4 = tid + u * 128;                                            \
            int a_row = f4 >> 2, grp = f4 & 3;                                 \
            As[buf][grp * 4 + 0][a_row] = a_ld[u].x;                           \
            As[buf][grp * 4 + 1][a_row] = a_ld[u].y;                           \
            As[buf][grp * 4 + 2][a_row] = a_ld[u].z;                           \
            As[buf][grp * 4 + 3][a_row] = a_ld[u].w;                           \
        }                                                                      \
        _Pragma("unroll")                                                      \
        for (int u = 0; u < 6; u++) {                                          \
            int idx = tid + u * 128;                                           \
            int bk = idx / 48, bc = idx - bk * 48;                             \
            Bs[buf][bk][bc] = b_ld[u];                                         \
        }                                                                      \
    }

    G2_LOAD(0)
    G2_STORE(0)
    __syncthreads();

    for (int kt = 0; kt < 8; kt++) {   // K = 128 = 8 * 16
        int cbuf = kt & 1;
        if (kt + 1 < 8) G2_LOAD((kt + 1) * 16)
#pragma unroll
        for (int kk = 0; kk < 16; kk++) {
            float4 a0 = *reinterpret_cast<const float4*>(&As[cbuf][kk][tr * 8]);
            float4 a1 = *reinterpret_cast<const float4*>(&As[cbuf][kk][tr * 8 + 4]);
            float a[8] = {a0.x, a0.y, a0.z, a0.w, a1.x, a1.y, a1.z, a1.w};
            float b[6];
#pragma unroll
            for (int j = 0; j < 6; j++) b[j] = Bs[cbuf][kk][tc * 6 + j];
#pragma unroll
            for (int i = 0; i < 8; i++)
#pragma unroll
                for (int j = 0; j < 6; j++) acc[i][j] += a[i] * b[j];
        }
        if (kt + 1 < 8) G2_STORE(cbuf ^ 1)
        __syncthreads();
    }

#pragma unroll
    for (int i = 0; i < 8; i++) {
        int gr = row0 + tr * 8 + i;
        if (gr < n) {
#pragma unroll
            for (int j = 0; j < 6; j++) {
                int col = tc * 6 + j;
                if (col < FOUT) g_H2[(size_t)gr * FOUT + col] = acc[i][j];
            }
        }
    }
#undef G2_LOAD
#undef G2_STORE
}

// ---------------- agg2 + bias + log_softmax ---------------------------------
__global__ __launch_bounds__(256) void k_agg2(
    const float* __restrict__ b2, float* __restrict__ out, int n)
{
    int gw = (blockIdx.x * blockDim.x + threadIdx.x) >> 5;
    int lane = threadIdx.x & 31;
    if (gw >= n) return;
    int i = gw;
    float di = g_dinv[i];
    bool v0 = lane < FOUT;
    bool v1 = (lane + 32) < FOUT;
    float a0 = v0 ? g_H2[(size_t)i * FOUT + lane]      * di * di : 0.f;
    float a1 = v1 ? g_H2[(size_t)i * FOUT + lane + 32] * di * di : 0.f;

    int beg = g_rowptr[i], end = g_rowptr[i + 1];
    for (int base = beg; base < end; base += 32) {
        int c = end - base; if (c > 32) c = 32;
        int s = 0; float w = 0.f;
        if (lane < c) { s = g_col[base + lane]; w = g_dinv[s] * di; }
        int k = 0;
        for (; k + 2 <= c; k += 2) {
            int   s0 = __shfl_sync(0xffffffffu, s, k);
            int   s1 = __shfl_sync(0xffffffffu, s, k + 1);
            float w0 = __shfl_sync(0xffffffffu, w, k);
            float w1 = __shfl_sync(0xffffffffu, w, k + 1);
            if (v0) a0 += g_H2[(size_t)s0 * FOUT + lane] * w0;
            if (v1) a1 += g_H2[(size_t)s0 * FOUT + lane + 32] * w0;
            if (v0) a0 += g_H2[(size_t)s1 * FOUT + lane] * w1;
            if (v1) a1 += g_H2[(size_t)s1 * FOUT + lane + 32] * w1;
        }
        for (; k < c; k++) {
            int   sk = __shfl_sync(0xffffffffu, s, k);
            float wk = __shfl_sync(0xffffffffu, w, k);
            if (v0) a0 += g_H2[(size_t)sk * FOUT + lane] * wk;
            if (v1) a1 += g_H2[(size_t)sk * FOUT + lane + 32] * wk;
        }
    }
    if (v0) a0 += b2[lane];
    if (v1) a1 += b2[lane + 32];

    float m = fmaxf(v0 ? a0 : -INFINITY, v1 ? a1 : -INFINITY);
#pragma unroll
    for (int off = 16; off; off >>= 1) m = fmaxf(m, __shfl_xor_sync(0xffffffffu, m, off));
    float e = (v0 ? expf(a0 - m) : 0.f) + (v1 ? expf(a1 - m) : 0.f);
#pragma unroll
    for (int off = 16; off; off >>= 1) e += __shfl_xor_sync(0xffffffffu, e, off);
    float ls = m + logf(e);
    if (v0) out[(size_t)i * FOUT + lane]      = a0 - ls;
    if (v1) out[(size_t)i * FOUT + lane + 32] = a1 - ls;
}

// ---------------- launch ----------------------------------------------------
extern "C" void kernel_launch(void* const* d_in, const int* in_sizes, int n_in,
                              void* d_out, int out_size)
{
    const float* x  = (const float*)d_in[0];
    const float* W1 = (const float*)d_in[1];
    const float* b1 = (const float*)d_in[2];
    const float* W2 = (const float*)d_in[3];
    const float* b2 = (const float*)d_in[4];
    const int*   ei = (const int*)d_in[5];   // int32 or int64; detected on device
    float* out = (float*)d_out;

    int n = in_sizes[0] / FIN;
    long long E = in_sizes[5] / 2;
    int nb = (n + 255) / 256;

    k_detect<<<1, 32>>>(ei);
    k_zero_cnt<<<nb, 256>>>(n);
    k_degree<<<(int)((E + 255) / 256), 256>>>(ei, E);
    k_part<<<nb, 256>>>(n);
    k_scan2<<<1, 256>>>(n, nb);
    k_write<<<nb, 256>>>(n);
    k_scatter<<<(int)((E + 255) / 256), 256>>>(ei, E);
    k_gemm1<<<(n + 127) / 128, 256>>>(x, W1, n);
    k_agg1<<<(n * 32 + 255) / 256, 256>>>(b1, n);
    k_gemm2<<<(n + 127) / 128, 128>>>(W2, n);
    k_agg2<<<(n * 32 + 255) / 256, 256>>>(b2, out, n);
}

// round 4
// speedup vs baseline: 2.5288x; 1.5531x over previous
#include <cuda_runtime.h>
#include <cuda_bf16.h>
#include <math.h>

// Problem constants (with headroom on N/E for safety)
#define FIN   500
#define FH    128
#define FOUT  47
#define NMAX  65536
#define EMAX  1048576

// ---------------- scratch (static device globals; no allocation) -------------
__device__ __align__(16) float g_dinv[NMAX];
__device__ int   g_cnt[NMAX];
__device__ int   g_rowptr[NMAX + 1];
__device__ int   g_wp[NMAX];
__device__ int   g_col[EMAX];
__device__ int   g_bsum[256];
__device__ int   g_boff[256];
__device__ __align__(16) float g_H1 [(size_t)NMAX * FH];   // x @ W1
__device__ __align__(16) float g_H1r[(size_t)NMAX * FH];   // relu(agg1 + b1)
__device__ __align__(16) float g_H2 [(size_t)NMAX * FOUT]; // H1r @ W2
__device__ int   g_is64;

__device__ __forceinline__ int ld_edge(const int* p, long long idx, int is64) {
    return is64 ? p[2 * idx] : p[idx];
}

// ---------------- dtype detection -------------------------------------------
__global__ void k_detect(const int* ei) {
    int lane = threadIdx.x;
    int nz = (ei[2 * lane + 1] != 0) ? 1 : 0;
    unsigned b = __ballot_sync(0xffffffffu, nz);
    if (lane == 0) g_is64 = (b == 0u) ? 1 : 0;
}

__global__ void k_zero_cnt(int n) {
    int i = blockIdx.x * blockDim.x + threadIdx.x;
    if (i < n) g_cnt[i] = 0;
}

__global__ void k_degree(const int* ei, long long E) {
    long long e = (long long)blockIdx.x * blockDim.x + threadIdx.x;
    if (e >= E) return;
    int is64 = g_is64;
    int dst = ld_edge(ei, E + e, is64);
    atomicAdd(&g_cnt[dst], 1);
}

// ---------------- 3-phase parallel scan --------------------------------------
__global__ void k_part(int n) {
    __shared__ int sh[8];
    int t = threadIdx.x;
    int i = blockIdx.x * 256 + t;
    int v = (i < n) ? g_cnt[i] : 0;
#pragma unroll
    for (int off = 16; off; off >>= 1) v += __shfl_xor_sync(0xffffffffu, v, off);
    if ((t & 31) == 0) sh[t >> 5] = v;
    __syncthreads();
    if (t < 8) {
        int s = sh[t];
#pragma unroll
        for (int off = 4; off; off >>= 1) s += __shfl_xor_sync(0xffu, s, off);
        if (t == 0) g_bsum[blockIdx.x] = s;
    }
}

__global__ void k_scan2(int n, int nb) {
    __shared__ int sh[256];
    int t = threadIdx.x;
    int v = (t < nb) ? g_bsum[t] : 0;
    sh[t] = v;
    __syncthreads();
#pragma unroll
    for (int off = 1; off < 256; off <<= 1) {
        int u = (t >= off) ? sh[t - off] : 0;
        __syncthreads();
        sh[t] += u;
        __syncthreads();
    }
    g_boff[t] = sh[t] - v;   // exclusive
    if (t == 255) g_rowptr[n] = sh[255];
}

__global__ void k_write(int n) {
    __shared__ int sh[256];
    int t = threadIdx.x;
    int i = blockIdx.x * 256 + t;
    int c = (i < n) ? g_cnt[i] : 0;
    sh[t] = c;
    __syncthreads();
#pragma unroll
    for (int off = 1; off < 256; off <<= 1) {
        int u = (t >= off) ? sh[t - off] : 0;
        __syncthreads();
        sh[t] += u;
        __syncthreads();
    }
    if (i < n) {
        int pos = g_boff[blockIdx.x] + sh[t] - c;
        g_rowptr[i] = pos;
        g_wp[i] = pos;
        g_dinv[i] = rsqrtf((float)(c + 1));   // +1 self-loop
    }
}

__global__ void k_scatter(const int* ei, long long E) {
    long long e = (long long)blockIdx.x * blockDim.x + threadIdx.x;
    if (e >= E) return;
    int is64 = g_is64;
    int src = ld_edge(ei, e, is64);
    int dst = ld_edge(ei, E + e, is64);
    int pos = atomicAdd(&g_wp[dst], 1);
    g_col[pos] = src;
}

// ---------------- mma helpers ------------------------------------------------
__device__ __forceinline__ void ldsm_x4(unsigned& r0, unsigned& r1, unsigned& r2, unsigned& r3,
                                        unsigned addr) {
    asm volatile("ldmatrix.sync.aligned.m8n8.x4.shared.b16 {%0,%1,%2,%3}, [%4];\n"
                 : "=r"(r0), "=r"(r1), "=r"(r2), "=r"(r3) : "r"(addr));
}
__device__ __forceinline__ void ldsm_x4_t(unsigned& r0, unsigned& r1, unsigned& r2, unsigned& r3,
                                          unsigned addr) {
    asm volatile("ldmatrix.sync.aligned.m8n8.x4.trans.shared.b16 {%0,%1,%2,%3}, [%4];\n"
                 : "=r"(r0), "=r"(r1), "=r"(r2), "=r"(r3) : "r"(addr));
}
__device__ __forceinline__ void mma_bf16(float* d, const unsigned* a, const unsigned* b) {
    asm volatile("mma.sync.aligned.m16n8k16.row.col.f32.bf16.bf16.f32 "
                 "{%0,%1,%2,%3}, {%4,%5,%6,%7}, {%8,%9}, {%0,%1,%2,%3};\n"
                 : "+f"(d[0]), "+f"(d[1]), "+f"(d[2]), "+f"(d[3])
                 : "r"(a[0]), "r"(a[1]), "r"(a[2]), "r"(a[3]), "r"(b[0]), "r"(b[1]));
}
// split a float4 into bf16 hi (rn) and bf16 lo = bf16(v - float(hi)), packed 2x per u32
__device__ __forceinline__ void cvt4(const float4 v, uint2& hi, uint2& lo) {
    __nv_bfloat16 h0 = __float2bfloat16(v.x), h1 = __float2bfloat16(v.y);
    __nv_bfloat16 h2 = __float2bfloat16(v.z), h3 = __float2bfloat16(v.w);
    __nv_bfloat16 l0 = __float2bfloat16(v.x - __bfloat162float(h0));
    __nv_bfloat16 l1 = __float2bfloat16(v.y - __bfloat162float(h1));
    __nv_bfloat16 l2 = __float2bfloat16(v.z - __bfloat162float(h2));
    __nv_bfloat16 l3 = __float2bfloat16(v.w - __bfloat162float(h3));
    hi.x = ((unsigned)__bfloat16_as_ushort(h1) << 16) | __bfloat16_as_ushort(h0);
    hi.y = ((unsigned)__bfloat16_as_ushort(h3) << 16) | __bfloat16_as_ushort(h2);
    lo.x = ((unsigned)__bfloat16_as_ushort(l1) << 16) | __bfloat16_as_ushort(l0);
    lo.y = ((unsigned)__bfloat16_as_ushort(l3) << 16) | __bfloat16_as_ushort(l2);
}

// ---------------- GEMM1: H1 = x @ W1 via bf16x2 tensor cores ----------------
// 128x128 block tile, BK=16, K padded to 512 (32 chunks). 8 warps = 4m x 2n,
// warp tile 32x64. D = Ah*Bh + Ah*Bl + Al*Bh in fp32 accum (~1e-5 rel err).
#define G1_KT 32
#define A_LDS 24    // halves per A row (16 + 8 pad) -> 48B stride, conflict-free
#define B_LDS 136   // halves per B row (128 + 8 pad) -> 272B stride, conflict-free
__global__ __launch_bounds__(256) void k_gemm1(
    const float* __restrict__ x, const float* __restrict__ W, int n)
{
    __shared__ __align__(16) __nv_bfloat16 Ah[2][128][A_LDS];
    __shared__ __align__(16) __nv_bfloat16 Al[2][128][A_LDS];
    __shared__ __align__(16) __nv_bfloat16 Bh[2][16][B_LDS];
    __shared__ __align__(16) __nv_bfloat16 Bl[2][16][B_LDS];

    int tid = threadIdx.x;
    int lane = tid & 31;
    int wid = tid >> 5;
    int wm = wid & 3;        // 4 warps along m, 32 rows each
    int wn = wid >> 2;       // 2 warps along n, 64 cols each
    int row0 = blockIdx.x * 128;

    float acc[2][8][4];
#pragma unroll
    for (int mi = 0; mi < 2; mi++)
#pragma unroll
        for (int ni = 0; ni < 8; ni++)
#pragma unroll
            for (int q = 0; q < 4; q++) acc[mi][ni][q] = 0.f;

    // ldmatrix lane-address offsets (bytes)
    unsigned ah_base = (unsigned)__cvta_generic_to_shared(&Ah[0][0][0]);
    unsigned al_base = (unsigned)__cvta_generic_to_shared(&Al[0][0][0]);
    unsigned bh_base = (unsigned)__cvta_generic_to_shared(&Bh[0][0][0]);
    unsigned bl_base = (unsigned)__cvta_generic_to_shared(&Bl[0][0][0]);
    const unsigned A_BUF = 128 * A_LDS * 2;   // bytes per A buffer
    const unsigned B_BUF = 16 * B_LDS * 2;    // bytes per B buffer
    unsigned a_lane = ((lane & 15) * A_LDS + (lane >> 4) * 8) * 2;
    unsigned b_lane = ((lane & 15) * B_LDS + (lane >> 4) * 8) * 2;

    float4 a_ld[2], b_ld[2];

#define G1_LOAD(k0)                                                            \
    {                                                                          \
        _Pragma("unroll")                                                      \
        for (int u = 0; u < 2; u++) {                                          \
            int f4 = tid + u * 256;                                            \
            int a_row = f4 >> 2, grp = f4 & 3;                                 \
            int gk = (k0) + grp * 4;                                           \
            int gr = row0 + a_row;                                             \
            if (gr < n && gk + 4 <= FIN)                                       \
                a_ld[u] = *reinterpret_cast<const float4*>(&x[(size_t)gr * FIN + gk]); \
            else a_ld[u] = make_float4(0.f, 0.f, 0.f, 0.f);                    \
            int bk = f4 >> 5, bc4 = f4 & 31;                                   \
            int gkb = (k0) + bk;                                               \
            if (gkb < FIN)                                                     \
                b_ld[u] = *reinterpret_cast<const float4*>(&W[(size_t)gkb * FH + bc4 * 4]); \
            else b_ld[u] = make_float4(0.f, 0.f, 0.f, 0.f);                    \
        }                                                                      \
    }

#define G1_STORE(buf)                                                          \
    {                                                                          \
        _Pragma("unroll")                                                      \
        for (int u = 0; u < 2; u++) {                                          \
            int f4 = tid + u * 256;                                            \
            int a_row = f4 >> 2, grp = f4 & 3;                                 \
            uint2 hi, lo;                                                      \
            cvt4(a_ld[u], hi, lo);                                             \
            *reinterpret_cast<uint2*>(&Ah[buf][a_row][grp * 4]) = hi;          \
            *reinterpret_cast<uint2*>(&Al[buf][a_row][grp * 4]) = lo;          \
            int bk = f4 >> 5, bc4 = f4 & 31;                                   \
            cvt4(b_ld[u], hi, lo);                                             \
            *reinterpret_cast<uint2*>(&Bh[buf][bk][bc4 * 4]) = hi;             \
            *reinterpret_cast<uint2*>(&Bl[buf][bk][bc4 * 4]) = lo;             \
        }                                                                      \
    }

    G1_LOAD(0)
    G1_STORE(0)
    __syncthreads();

    for (int kt = 0; kt < G1_KT; kt++) {
        int cbuf = kt & 1;
        if (kt + 1 < G1_KT) G1_LOAD((kt + 1) * 16)

        // load fragments
        unsigned ah[2][4], al[2][4], bh[8][2], bl[8][2];
#pragma unroll
        for (int mi = 0; mi < 2; mi++) {
            unsigned roff = (unsigned)((wm * 32 + mi * 16) * A_LDS * 2);
            ldsm_x4(ah[mi][0], ah[mi][1], ah[mi][2], ah[mi][3],
                    ah_base + cbuf * A_BUF + roff + a_lane);
            ldsm_x4(al[mi][0], al[mi][1], al[mi][2], al[mi][3],
                    al_base + cbuf * A_BUF + roff + a_lane);
        }
#pragma unroll
        for (int p = 0; p < 4; p++) {
            unsigned coff = (unsigned)((wn * 64 + p * 16) * 2);
            ldsm_x4_t(bh[2*p][0], bh[2*p][1], bh[2*p+1][0], bh[2*p+1][1],
                      bh_base + cbuf * B_BUF + coff + b_lane);
            ldsm_x4_t(bl[2*p][0], bl[2*p][1], bl[2*p+1][0], bl[2*p+1][1],
                      bl_base + cbuf * B_BUF + coff + b_lane);
        }

#pragma unroll
        for (int mi = 0; mi < 2; mi++)
#pragma unroll
            for (int ni = 0; ni < 8; ni++) {
                mma_bf16(acc[mi][ni], ah[mi], bh[ni]);
                mma_bf16(acc[mi][ni], ah[mi], bl[ni]);
                mma_bf16(acc[mi][ni], al[mi], bh[ni]);
            }

        if (kt + 1 < G1_KT) G1_STORE(cbuf ^ 1)
        __syncthreads();
    }

    // epilogue: c0,c1 -> (r, c), (r, c+1); c2,c3 -> (r+8, ...)
    int rbase = row0 + wm * 32 + (lane >> 2);
    int cbase = wn * 64 + (lane & 3) * 2;
#pragma unroll
    for (int mi = 0; mi < 2; mi++) {
#pragma unroll
        for (int ni = 0; ni < 8; ni++) {
            int col = cbase + ni * 8;
            int r0 = rbase + mi * 16;
            if (r0 < n)
                *reinterpret_cast<float2*>(&g_H1[(size_t)r0 * FH + col]) =
                    make_float2(acc[mi][ni][0], acc[mi][ni][1]);
            if (r0 + 8 < n)
                *reinterpret_cast<float2*>(&g_H1[(size_t)(r0 + 8) * FH + col]) =
                    make_float2(acc[mi][ni][2], acc[mi][ni][3]);
        }
    }
#undef G1_LOAD
#undef G1_STORE
}

// ---------------- agg1: H1r = relu( Ahat @ H1 + b1 ) ------------------------
__global__ __launch_bounds__(256) void k_agg1(const float* __restrict__ b1, int n) {
    int gw = (blockIdx.x * blockDim.x + threadIdx.x) >> 5;
    int lane = threadIdx.x & 31;
    if (gw >= n) return;
    int i = gw;
    float di = g_dinv[i];
    const float4* H = reinterpret_cast<const float4*>(g_H1);
    float4 h = H[(size_t)i * 32 + lane];
    float sw = di * di;
    float4 acc = make_float4(h.x * sw, h.y * sw, h.z * sw, h.w * sw);

    int beg = g_rowptr[i], end = g_rowptr[i + 1];
    for (int base = beg; base < end; base += 32) {
        int c = end - base; if (c > 32) c = 32;
        int s = 0; float w = 0.f;
        if (lane < c) { s = g_col[base + lane]; w = g_dinv[s] * di; }
        int k = 0;
        for (; k + 4 <= c; k += 4) {
            int   s0 = __shfl_sync(0xffffffffu, s, k);
            int   s1 = __shfl_sync(0xffffffffu, s, k + 1);
            int   s2 = __shfl_sync(0xffffffffu, s, k + 2);
            int   s3 = __shfl_sync(0xffffffffu, s, k + 3);
            float w0 = __shfl_sync(0xffffffffu, w, k);
            float w1 = __shfl_sync(0xffffffffu, w, k + 1);
            float w2 = __shfl_sync(0xffffffffu, w, k + 2);
            float w3 = __shfl_sync(0xffffffffu, w, k + 3);
            float4 v0 = H[(size_t)s0 * 32 + lane];
            float4 v1 = H[(size_t)s1 * 32 + lane];
            float4 v2 = H[(size_t)s2 * 32 + lane];
            float4 v3 = H[(size_t)s3 * 32 + lane];
            acc.x += v0.x * w0; acc.y += v0.y * w0; acc.z += v0.z * w0; acc.w += v0.w * w0;
            acc.x += v1.x * w1; acc.y += v1.y * w1; acc.z += v1.z * w1; acc.w += v1.w * w1;
            acc.x += v2.x * w2; acc.y += v2.y * w2; acc.z += v2.z * w2; acc.w += v2.w * w2;
            acc.x += v3.x * w3; acc.y += v3.y * w3; acc.z += v3.z * w3; acc.w += v3.w * w3;
        }
        for (; k < c; k++) {
            int   sk = __shfl_sync(0xffffffffu, s, k);
            float wk = __shfl_sync(0xffffffffu, w, k);
            float4 v = H[(size_t)sk * 32 + lane];
            acc.x += v.x * wk; acc.y += v.y * wk; acc.z += v.z * wk; acc.w += v.w * wk;
        }
    }
    float4 b = reinterpret_cast<const float4*>(b1)[lane];
    float4 o = make_float4(fmaxf(acc.x + b.x, 0.f), fmaxf(acc.y + b.y, 0.f),
                           fmaxf(acc.z + b.z, 0.f), fmaxf(acc.w + b.w, 0.f));
    reinterpret_cast<float4*>(g_H1r)[(size_t)i * 32 + lane] = o;
}

// ---------------- GEMM2: H2 = H1r @ W2  (n x 128) @ (128 x 47) --------------
__global__ __launch_bounds__(128, 4) void k_gemm2(const float* __restrict__ W2, int n) {
    __shared__ __align__(16) float As[2][16][132];
    __shared__ __align__(16) float Bs[2][16][48];

    int tid = threadIdx.x;
    int row0 = blockIdx.x * 128;
    int tr = tid >> 3;  // 0..15 -> rows tr*8
    int tc = tid & 7;   // 0..7  -> cols tc*6

    float acc[8][6];
#pragma unroll
    for (int i = 0; i < 8; i++)
#pragma unroll
        for (int j = 0; j < 6; j++) acc[i][j] = 0.f;

    float4 a_ld[4];
    float  b_ld[6];

#define G2_LOAD(k0)                                                            \
    {                                                                          \
        _Pragma("unroll")                                                      \
        for (int u = 0; u < 4; u++) {                                          \
            int f4 = tid + u * 128;                                            \
            int a_row = f4 >> 2, grp = f4 & 3;                                 \
            int gr = row0 + a_row;                                             \
            a_ld[u] = (gr < n)                                                 \
                ? *reinterpret_cast<const float4*>(&g_H1r[(size_t)gr * FH + (k0) + grp * 4]) \
                : make_float4(0.f, 0.f, 0.f, 0.f);                             \
        }                                                                      \
        _Pragma("unroll")                                                      \
        for (int u = 0; u < 6; u++) {                                          \
            int idx = tid + u * 128;                                           \
            int bk = idx / 48, bc = idx - bk * 48;                             \
            b_ld[u] = (bc < FOUT) ? W2[(size_t)((k0) + bk) * FOUT + bc] : 0.f; \
        }                                                                      \
    }

#define G2_STORE(buf)                                                          \
    {                                                                          \
        _Pragma("unroll")                                                      \
        for (int u = 0; u < 4; u++) {                                          \
            int f4 = tid + u * 128;                                            \
            int a_row = f4 >> 2, grp = f4 & 3;                                 \
            As[buf][grp * 4 + 0][a_row] = a_ld[u].x;                           \
            As[buf][grp * 4 + 1][a_row] = a_ld[u].y;                           \
            As[buf][grp * 4 + 2][a_row] = a_ld[u].z;                           \
            As[buf][grp * 4 + 3][a_row] = a_ld[u].w;                           \
        }                                                                      \
        _Pragma("unroll")                                                      \
        for (int u = 0; u < 6; u++) {                                          \
            int idx = tid + u * 128;                                           \
            int bk = idx / 48, bc = idx - bk * 48;                             \
            Bs[buf][bk][bc] = b_ld[u];                                         \
        }                                                                      \
    }

    G2_LOAD(0)
    G2_STORE(0)
    __syncthreads();

    for (int kt = 0; kt < 8; kt++) {   // K = 128 = 8 * 16
        int cbuf = kt & 1;
        if (kt + 1 < 8) G2_LOAD((kt + 1) * 16)
#pragma unroll
        for (int kk = 0; kk < 16; kk++) {
            float4 a0 = *reinterpret_cast<const float4*>(&As[cbuf][kk][tr * 8]);
            float4 a1 = *reinterpret_cast<const float4*>(&As[cbuf][kk][tr * 8 + 4]);
            float a[8] = {a0.x, a0.y, a0.z, a0.w, a1.x, a1.y, a1.z, a1.w};
            float b[6];
#pragma unroll
            for (int j = 0; j < 6; j++) b[j] = Bs[cbuf][kk][tc * 6 + j];
#pragma unroll
            for (int i = 0; i < 8; i++)
#pragma unroll
                for (int j = 0; j < 6; j++) acc[i][j] += a[i] * b[j];
        }
        if (kt + 1 < 8) G2_STORE(cbuf ^ 1)
        __syncthreads();
    }

#pragma unroll
    for (int i = 0; i < 8; i++) {
        int gr = row0 + tr * 8 + i;
        if (gr < n) {
#pragma unroll
            for (int j = 0; j < 6; j++) {
                int col = tc * 6 + j;
                if (col < FOUT) g_H2[(size_t)gr * FOUT + col] = acc[i][j];
            }
        }
    }
#undef G2_LOAD
#undef G2_STORE
}

// ---------------- agg2 + bias + log_softmax ---------------------------------
__global__ __launch_bounds__(256) void k_agg2(
    const float* __restrict__ b2, float* __restrict__ out, int n)
{
    int gw = (blockIdx.x * blockDim.x + threadIdx.x) >> 5;
    int lane = threadIdx.x & 31;
    if (gw >= n) return;
    int i = gw;
    float di = g_dinv[i];
    bool v0 = lane < FOUT;
    bool v1 = (lane + 32) < FOUT;
    float a0 = v0 ? g_H2[(size_t)i * FOUT + lane]      * di * di : 0.f;
    float a1 = v1 ? g_H2[(size_t)i * FOUT + lane + 32] * di * di : 0.f;

    int beg = g_rowptr[i], end = g_rowptr[i + 1];
    for (int base = beg; base < end; base += 32) {
        int c = end - base; if (c > 32) c = 32;
        int s = 0; float w = 0.f;
        if (lane < c) { s = g_col[base + lane]; w = g_dinv[s] * di; }
        int k = 0;
        for (; k + 2 <= c; k += 2) {
            int   s0 = __shfl_sync(0xffffffffu, s, k);
            int   s1 = __shfl_sync(0xffffffffu, s, k + 1);
            float w0 = __shfl_sync(0xffffffffu, w, k);
            float w1 = __shfl_sync(0xffffffffu, w, k + 1);
            if (v0) a0 += g_H2[(size_t)s0 * FOUT + lane] * w0;
            if (v1) a1 += g_H2[(size_t)s0 * FOUT + lane + 32] * w0;
            if (v0) a0 += g_H2[(size_t)s1 * FOUT + lane] * w1;
            if (v1) a1 += g_H2[(size_t)s1 * FOUT + lane + 32] * w1;
        }
        for (; k < c; k++) {
            int   sk = __shfl_sync(0xffffffffu, s, k);
            float wk = __shfl_sync(0xffffffffu, w, k);
            if (v0) a0 += g_H2[(size_t)sk * FOUT + lane] * wk;
            if (v1) a1 += g_H2[(size_t)sk * FOUT + lane + 32] * wk;
        }
    }
    if (v0) a0 += b2[lane];
    if (v1) a1 += b2[lane + 32];

    float m = fmaxf(v0 ? a0 : -INFINITY, v1 ? a1 : -INFINITY);
#pragma unroll
    for (int off = 16; off; off >>= 1) m = fmaxf(m, __shfl_xor_sync(0xffffffffu, m, off));
    float e = (v0 ? expf(a0 - m) : 0.f) + (v1 ? expf(a1 - m) : 0.f);
#pragma unroll
    for (int off = 16; off; off >>= 1) e += __shfl_xor_sync(0xffffffffu, e, off);
    float ls = m + logf(e);
    if (v0) out[(size_t)i * FOUT + lane]      = a0 - ls;
    if (v1) out[(size_t)i * FOUT + lane + 32] = a1 - ls;
}

// ---------------- launch ----------------------------------------------------
extern "C" void kernel_launch(void* const* d_in, const int* in_sizes, int n_in,
                              void* d_out, int out_size)
{
    const float* x  = (const float*)d_in[0];
    const float* W1 = (const float*)d_in[1];
    const float* b1 = (const float*)d_in[2];
    const float* W2 = (const float*)d_in[3];
    const float* b2 = (const float*)d_in[4];
    const int*   ei = (const int*)d_in[5];   // int32 or int64; detected on device
    float* out = (float*)d_out;

    int n = in_sizes[0] / FIN;
    long long E = in_sizes[5] / 2;
    int nb = (n + 255) / 256;

    k_detect<<<1, 32>>>(ei);
    k_zero_cnt<<<nb, 256>>>(n);
    k_degree<<<(int)((E + 255) / 256), 256>>>(ei, E);
    k_part<<<nb, 256>>>(n);
    k_scan2<<<1, 256>>>(n, nb);
    k_write<<<nb, 256>>>(n);
    k_scatter<<<(int)((E + 255) / 256), 256>>>(ei, E);
    k_gemm1<<<(n + 127) / 128, 256>>>(x, W1, n);
    k_agg1<<<(n * 32 + 255) / 256, 256>>>(b1, n);
    k_gemm2<<<(n + 127) / 128, 128>>>(W2, n);
    k_agg2<<<(n * 32 + 255) / 256, 256>>>(b2, out, n);
}

// round 6
// speedup vs baseline: 2.5999x; 1.0282x over previous
#include <cuda_runtime.h>
#include <cuda_bf16.h>
#include <math.h>

// Problem constants (with headroom on N/E for safety)
#define FIN   500
#define FH    128
#define FOUT  47
#define NMAX  65536
#define EMAX  1048576

// ---------------- scratch (static device globals; no allocation) -------------
__device__ __align__(16) float g_dinv[NMAX];
__device__ int   g_cnt[NMAX];
__device__ int   g_rowptr[NMAX + 1];
__device__ int   g_wp[NMAX];
__device__ int   g_col[EMAX];
__device__ int   g_bsum[256];
__device__ __align__(16) unsigned g_H1bf[(size_t)NMAX * 64];   // x @ W1, bf16x2 packed
__device__ __align__(16) float g_H1r[(size_t)NMAX * FH];        // relu(agg1 + b1)
__device__ __align__(16) float g_H2 [(size_t)NMAX * FOUT];      // H1r @ W2
__device__ int   g_is64;

__device__ __forceinline__ int ld_edge(const int* p, long long idx, int is64) {
    return is64 ? p[2 * idx] : p[idx];
}

// ---------------- init: zero counters + dtype detect (fused) -----------------
// int64 LE: odd 32-bit words are 0 (values < 50000). int32: odd words random.
__global__ void k_init(const int* ei, int n) {
    int i = blockIdx.x * blockDim.x + threadIdx.x;
    if (i < n) g_cnt[i] = 0;
    if (blockIdx.x == 0 && threadIdx.x < 32) {
        int lane = threadIdx.x;
        int nz = (ei[2 * lane + 1] != 0) ? 1 : 0;
        unsigned b = __ballot_sync(0xffffffffu, nz);
        if (lane == 0) g_is64 = (b == 0u) ? 1 : 0;
    }
}

__global__ void k_degree(const int* ei, long long E) {
    long long e = (long long)blockIdx.x * blockDim.x + threadIdx.x;
    if (e >= E) return;
    int is64 = g_is64;
    int dst = ld_edge(ei, E + e, is64);
    atomicAdd(&g_cnt[dst], 1);
}

// ---------------- 2-phase parallel scan --------------------------------------
// phase 1: per-block (256 elems) reduction -> g_bsum
__global__ void k_part(int n) {
    __shared__ int sh[8];
    int t = threadIdx.x;
    int i = blockIdx.x * 256 + t;
    int v = (i < n) ? g_cnt[i] : 0;
#pragma unroll
    for (int off = 16; off; off >>= 1) v += __shfl_xor_sync(0xffffffffu, v, off);
    if ((t & 31) == 0) sh[t >> 5] = v;
    __syncthreads();
    if (t < 8) {
        int s = sh[t];
#pragma unroll
        for (int off = 4; off; off >>= 1) s += __shfl_xor_sync(0xffu, s, off);
        if (t == 0) g_bsum[blockIdx.x] = s;
    }
}

// phase 2: each block reduces preceding partials itself, then internal scan
__global__ void k_write(int n, int nb) {
    __shared__ int sh[256];
    __shared__ int red[8];
    int t = threadIdx.x;
    int b = blockIdx.x;

    // boff = sum of g_bsum[j] for j < b   (block-wide reduction)
    int v = (t < b && t < nb) ? g_bsum[t] : 0;
#pragma unroll
    for (int off = 16; off; off >>= 1) v += __shfl_xor_sync(0xffffffffu, v, off);
    if ((t & 31) == 0) red[t >> 5] = v;
    __syncthreads();
    int boff;
    {
        int s = (t < 8) ? red[t] : 0;
        if (t < 8) {
#pragma unroll
            for (int off = 4; off; off >>= 1) s += __shfl_xor_sync(0xffu, s, off);
            if (t == 0) red[0] = s;
        }
        __syncthreads();
        boff = red[0];
    }

    int i = b * 256 + t;
    int c = (i < n) ? g_cnt[i] : 0;
    sh[t] = c;
    __syncthreads();
#pragma unroll
    for (int off = 1; off < 256; off <<= 1) {
        int u = (t >= off) ? sh[t - off] : 0;
        __syncthreads();
        sh[t] += u;
        __syncthreads();
    }
    if (i < n) {
        int pos = boff + sh[t] - c;
        g_rowptr[i] = pos;
        g_wp[i] = pos;
        g_dinv[i] = rsqrtf((float)(c + 1));   // +1 self-loop
    }
    if (b == nb - 1 && t == 255) g_rowptr[n] = boff + sh[255];
}

__global__ void k_scatter(const int* ei, long long E) {
    long long e = (long long)blockIdx.x * blockDim.x + threadIdx.x;
    if (e >= E) return;
    int is64 = g_is64;
    int src = ld_edge(ei, e, is64);
    int dst = ld_edge(ei, E + e, is64);
    int pos = atomicAdd(&g_wp[dst], 1);
    g_col[pos] = src;
}

// ---------------- mma helpers ------------------------------------------------
__device__ __forceinline__ void ldsm_x4(unsigned& r0, unsigned& r1, unsigned& r2, unsigned& r3,
                                        unsigned addr) {
    asm volatile("ldmatrix.sync.aligned.m8n8.x4.shared.b16 {%0,%1,%2,%3}, [%4];\n"
                 : "=r"(r0), "=r"(r1), "=r"(r2), "=r"(r3) : "r"(addr));
}
__device__ __forceinline__ void ldsm_x4_t(unsigned& r0, unsigned& r1, unsigned& r2, unsigned& r3,
                                          unsigned addr) {
    asm volatile("ldmatrix.sync.aligned.m8n8.x4.trans.shared.b16 {%0,%1,%2,%3}, [%4];\n"
                 : "=r"(r0), "=r"(r1), "=r"(r2), "=r"(r3) : "r"(addr));
}
__device__ __forceinline__ void mma_bf16(float* d, const unsigned* a, const unsigned* b) {
    asm volatile("mma.sync.aligned.m16n8k16.row.col.f32.bf16.bf16.f32 "
                 "{%0,%1,%2,%3}, {%4,%5,%6,%7}, {%8,%9}, {%0,%1,%2,%3};\n"
                 : "+f"(d[0]), "+f"(d[1]), "+f"(d[2]), "+f"(d[3])
                 : "r"(a[0]), "r"(a[1]), "r"(a[2]), "r"(a[3]), "r"(b[0]), "r"(b[1]));
}
// split a float4 into bf16 hi (rn) and bf16 lo = bf16(v - float(hi)), packed 2x per u32
__device__ __forceinline__ void cvt4(const float4 v, uint2& hi, uint2& lo) {
    __nv_bfloat16 h0 = __float2bfloat16(v.x), h1 = __float2bfloat16(v.y);
    __nv_bfloat16 h2 = __float2bfloat16(v.z), h3 = __float2bfloat16(v.w);
    __nv_bfloat16 l0 = __float2bfloat16(v.x - __bfloat162float(h0));
    __nv_bfloat16 l1 = __float2bfloat16(v.y - __bfloat162float(h1));
    __nv_bfloat16 l2 = __float2bfloat16(v.z - __bfloat162float(h2));
    __nv_bfloat16 l3 = __float2bfloat16(v.w - __bfloat162float(h3));
    hi.x = ((unsigned)__bfloat16_as_ushort(h1) << 16) | __bfloat16_as_ushort(h0);
    hi.y = ((unsigned)__bfloat16_as_ushort(h3) << 16) | __bfloat16_as_ushort(h2);
    lo.x = ((unsigned)__bfloat16_as_ushort(l1) << 16) | __bfloat16_as_ushort(l0);
    lo.y = ((unsigned)__bfloat16_as_ushort(l3) << 16) | __bfloat16_as_ushort(l2);
}
__device__ __forceinline__ unsigned pack_bf16(float a, float b) {
    return ((unsigned)__bfloat16_as_ushort(__float2bfloat16(b)) << 16) |
           __bfloat16_as_ushort(__float2bfloat16(a));
}

// ---------------- GEMM1: H1 = x @ W1 via bf16x2 tensor cores ----------------
// 128x128 block tile, BK=16, K padded to 512 (32 chunks). 8 warps = 4m x 2n.
// Output written as packed bf16x2 (consumed by agg1).
#define G1_KT 32
#define A_LDS 24
#define B_LDS 136
__global__ __launch_bounds__(256) void k_gemm1(
    const float* __restrict__ x, const float* __restrict__ W, int n)
{
    __shared__ __align__(16) __nv_bfloat16 Ah[2][128][A_LDS];
    __shared__ __align__(16) __nv_bfloat16 Al[2][128][A_LDS];
    __shared__ __align__(16) __nv_bfloat16 Bh[2][16][B_LDS];
    __shared__ __align__(16) __nv_bfloat16 Bl[2][16][B_LDS];

    int tid = threadIdx.x;
    int lane = tid & 31;
    int wid = tid >> 5;
    int wm = wid & 3;
    int wn = wid >> 2;
    int row0 = blockIdx.x * 128;

    float acc[2][8][4];
#pragma unroll
    for (int mi = 0; mi < 2; mi++)
#pragma unroll
        for (int ni = 0; ni < 8; ni++)
#pragma unroll
            for (int q = 0; q < 4; q++) acc[mi][ni][q] = 0.f;

    unsigned ah_base = (unsigned)__cvta_generic_to_shared(&Ah[0][0][0]);
    unsigned al_base = (unsigned)__cvta_generic_to_shared(&Al[0][0][0]);
    unsigned bh_base = (unsigned)__cvta_generic_to_shared(&Bh[0][0][0]);
    unsigned bl_base = (unsigned)__cvta_generic_to_shared(&Bl[0][0][0]);
    const unsigned A_BUF = 128 * A_LDS * 2;
    const unsigned B_BUF = 16 * B_LDS * 2;
    unsigned a_lane = ((lane & 15) * A_LDS + (lane >> 4) * 8) * 2;
    unsigned b_lane = ((lane & 15) * B_LDS + (lane >> 4) * 8) * 2;

    float4 a_ld[2], b_ld[2];

#define G1_LOAD(k0)                                                            \
    {                                                                          \
        _Pragma("unroll")                                                      \
        for (int u = 0; u < 2; u++) {                                          \
            int f4 = tid + u * 256;                                            \
            int a_row = f4 >> 2, grp = f4 & 3;                                 \
            int gk = (k0) + grp * 4;                                           \
            int gr = row0 + a_row;                                             \
            if (gr < n && gk + 4 <= FIN)                                       \
                a_ld[u] = *reinterpret_cast<const float4*>(&x[(size_t)gr * FIN + gk]); \
            else a_ld[u] = make_float4(0.f, 0.f, 0.f, 0.f);                    \
            int bk = f4 >> 5, bc4 = f4 & 31;                                   \
            int gkb = (k0) + bk;                                               \
            if (gkb < FIN)                                                     \
                b_ld[u] = *reinterpret_cast<const float4*>(&W[(size_t)gkb * FH + bc4 * 4]); \
            else b_ld[u] = make_float4(0.f, 0.f, 0.f, 0.f);                    \
        }                                                                      \
    }

#define G1_STORE(buf)                                                          \
    {                                                                          \
        _Pragma("unroll")                                                      \
        for (int u = 0; u < 2; u++) {                                          \
            int f4 = tid + u * 256;                                            \
            int a_row = f4 >> 2, grp = f4 & 3;                                 \
            uint2 hi, lo;                                                      \
            cvt4(a_ld[u], hi, lo);                                             \
            *reinterpret_cast<uint2*>(&Ah[buf][a_row][grp * 4]) = hi;          \
            *reinterpret_cast<uint2*>(&Al[buf][a_row][grp * 4]) = lo;          \
            int bk = f4 >> 5, bc4 = f4 & 31;                                   \
            cvt4(b_ld[u], hi, lo);                                             \
            *reinterpret_cast<uint2*>(&Bh[buf][bk][bc4 * 4]) = hi;             \
            *reinterpret_cast<uint2*>(&Bl[buf][bk][bc4 * 4]) = lo;             \
        }                                                                      \
    }

    G1_LOAD(0)
    G1_STORE(0)
    __syncthreads();

    for (int kt = 0; kt < G1_KT; kt++) {
        int cbuf = kt & 1;
        if (kt + 1 < G1_KT) G1_LOAD((kt + 1) * 16)

        unsigned ah[2][4], al[2][4], bh[8][2], bl[8][2];
#pragma unroll
        for (int mi = 0; mi < 2; mi++) {
            unsigned roff = (unsigned)((wm * 32 + mi * 16) * A_LDS * 2);
            ldsm_x4(ah[mi][0], ah[mi][1], ah[mi][2], ah[mi][3],
                    ah_base + cbuf * A_BUF + roff + a_lane);
            ldsm_x4(al[mi][0], al[mi][1], al[mi][2], al[mi][3],
                    al_base + cbuf * A_BUF + roff + a_lane);
        }
#pragma unroll
        for (int p = 0; p < 4; p++) {
            unsigned coff = (unsigned)((wn * 64 + p * 16) * 2);
            ldsm_x4_t(bh[2*p][0], bh[2*p][1], bh[2*p+1][0], bh[2*p+1][1],
                      bh_base + cbuf * B_BUF + coff + b_lane);
            ldsm_x4_t(bl[2*p][0], bl[2*p][1], bl[2*p+1][0], bl[2*p+1][1],
                      bl_base + cbuf * B_BUF + coff + b_lane);
        }

#pragma unroll
        for (int mi = 0; mi < 2; mi++)
#pragma unroll
            for (int ni = 0; ni < 8; ni++) {
                mma_bf16(acc[mi][ni], ah[mi], bh[ni]);
                mma_bf16(acc[mi][ni], ah[mi], bl[ni]);
                mma_bf16(acc[mi][ni], al[mi], bh[ni]);
            }

        if (kt + 1 < G1_KT) G1_STORE(cbuf ^ 1)
        __syncthreads();
    }

    // epilogue -> packed bf16x2. acc[..][0,1] = cols (c,c+1); [2,3] = row+8.
    int rbase = row0 + wm * 32 + (lane >> 2);
    int cbase = wn * 64 + (lane & 3) * 2;
#pragma unroll
    for (int mi = 0; mi < 2; mi++) {
#pragma unroll
        for (int ni = 0; ni < 8; ni++) {
            int col = cbase + ni * 8;      // even
            int r0 = rbase + mi * 16;
            if (r0 < n)
                g_H1bf[(size_t)r0 * 64 + (col >> 1)] =
                    pack_bf16(acc[mi][ni][0], acc[mi][ni][1]);
            if (r0 + 8 < n)
                g_H1bf[(size_t)(r0 + 8) * 64 + (col >> 1)] =
                    pack_bf16(acc[mi][ni][2], acc[mi][ni][3]);
        }
    }
#undef G1_LOAD
#undef G1_STORE
}

// ---------------- agg1: H1r = relu( Ahat @ H1 + b1 ) ------------------------
// One warp per node; lane covers 4 features (uint2 of bf16x2). 256B/row gathers.
__device__ __forceinline__ void bf2_fma(float4& acc, uint2 u, float w) {
    float f0 = __uint_as_float(u.x << 16);
    float f1 = __uint_as_float(u.x & 0xffff0000u);
    float f2 = __uint_as_float(u.y << 16);
    float f3 = __uint_as_float(u.y & 0xffff0000u);
    acc.x += f0 * w; acc.y += f1 * w; acc.z += f2 * w; acc.w += f3 * w;
}
__global__ __launch_bounds__(256) void k_agg1(const float* __restrict__ b1, int n) {
    int gw = (blockIdx.x * blockDim.x + threadIdx.x) >> 5;
    int lane = threadIdx.x & 31;
    if (gw >= n) return;
    int i = gw;
    float di = g_dinv[i];
    const uint2* H = reinterpret_cast<const uint2*>(g_H1bf);
    float4 acc = make_float4(0.f, 0.f, 0.f, 0.f);
    bf2_fma(acc, H[(size_t)i * 32 + lane], di * di);   // self loop

    int beg = g_rowptr[i], end = g_rowptr[i + 1];
    for (int base = beg; base < end; base += 32) {
        int c = end - base; if (c > 32) c = 32;
        int s = 0; float w = 0.f;
        if (lane < c) { s = g_col[base + lane]; w = g_dinv[s] * di; }
        int k = 0;
        for (; k + 4 <= c; k += 4) {
            int   s0 = __shfl_sync(0xffffffffu, s, k);
            int   s1 = __shfl_sync(0xffffffffu, s, k + 1);
            int   s2 = __shfl_sync(0xffffffffu, s, k + 2);
            int   s3 = __shfl_sync(0xffffffffu, s, k + 3);
            float w0 = __shfl_sync(0xffffffffu, w, k);
            float w1 = __shfl_sync(0xffffffffu, w, k + 1);
            float w2 = __shfl_sync(0xffffffffu, w, k + 2);
            float w3 = __shfl_sync(0xffffffffu, w, k + 3);
            uint2 v0 = H[(size_t)s0 * 32 + lane];
            uint2 v1 = H[(size_t)s1 * 32 + lane];
            uint2 v2 = H[(size_t)s2 * 32 + lane];
            uint2 v3 = H[(size_t)s3 * 32 + lane];
            bf2_fma(acc, v0, w0);
            bf2_fma(acc, v1, w1);
            bf2_fma(acc, v2, w2);
            bf2_fma(acc, v3, w3);
        }
        for (; k < c; k++) {
            int   sk = __shfl_sync(0xffffffffu, s, k);
            float wk = __shfl_sync(0xffffffffu, w, k);
            bf2_fma(acc, H[(size_t)sk * 32 + lane], wk);
        }
    }
    float4 b = reinterpret_cast<const float4*>(b1)[lane];
    float4 o = make_float4(fmaxf(acc.x + b.x, 0.f), fmaxf(acc.y + b.y, 0.f),
                           fmaxf(acc.z + b.z, 0.f), fmaxf(acc.w + b.w, 0.f));
    reinterpret_cast<float4*>(g_H1r)[(size_t)i * 32 + lane] = o;
}

// ---------------- GEMM2: H2 = H1r @ W2  (n x 128) @ (128 x 47) --------------
__global__ __launch_bounds__(128, 4) void k_gemm2(const float* __restrict__ W2, int n) {
    __shared__ __align__(16) float As[2][16][132];
    __shared__ __align__(16) float Bs[2][16][48];

    int tid = threadIdx.x;
    int row0 = blockIdx.x * 128;
    int tr = tid >> 3;
    int tc = tid & 7;

    float acc[8][6];
#pragma unroll
    for (int i = 0; i < 8; i++)
#pragma unroll
        for (int j = 0; j < 6; j++) acc[i][j] = 0.f;

    float4 a_ld[4];
    float  b_ld[6];

#define G2_LOAD(k0)                                                            \
    {                                                                          \
        _Pragma("unroll")                                                      \
        for (int u = 0; u < 4; u++) {                                          \
            int f4 = tid + u * 128;                                            \
            int a_row = f4 >> 2, grp = f4 & 3;                                 \
            int gr = row0 + a_row;                                             \
            a_ld[u] = (gr < n)                                                 \
                ? *reinterpret_cast<const float4*>(&g_H1r[(size_t)gr * FH + (k0) + grp * 4]) \
                : make_float4(0.f, 0.f, 0.f, 0.f);                             \
        }                                                                      \
        _Pragma("unroll")                                                      \
        for (int u = 0; u < 6; u++) {                                          \
            int idx = tid + u * 128;                                           \
            int bk = idx / 48, bc = idx - bk * 48;                             \
            b_ld[u] = (bc < FOUT) ? W2[(size_t)((k0) + bk) * FOUT + bc] : 0.f; \
        }                                                                      \
    }

#define G2_STORE(buf)                                                          \
    {                                                                          \
        _Pragma("unroll")                                                      \
        for (int u = 0; u < 4; u++) {                                          \
            int f4 = tid + u * 128;                                            \
            int a_row = f4 >> 2, grp = f4 & 3;                                 \
            As[buf][grp * 4 + 0][a_row] = a_ld[u].x;                           \
            As[buf][grp * 4 + 1][a_row] = a_ld[u].y;                           \
            As[buf][grp * 4 + 2][a_row] = a_ld[u].z;                           \
            As[buf][grp * 4 + 3][a_row] = a_ld[u].w;                           \
        }                                                                      \
        _Pragma("unroll")                                                      \
        for (int u = 0; u < 6; u++) {                                          \
            int idx = tid + u * 128;                                           \
            int bk = idx / 48, bc = idx - bk * 48;                             \
            Bs[buf][bk][bc] = b_ld[u];                                         \
        }                                                                      \
    }

    G2_LOAD(0)
    G2_STORE(0)
    __syncthreads();

    for (int kt = 0; kt < 8; kt++) {
        int cbuf = kt & 1;
        if (kt + 1 < 8) G2_LOAD((kt + 1) * 16)
#pragma unroll
        for (int kk = 0; kk < 16; kk++) {
            float4 a0 = *reinterpret_cast<const float4*>(&As[cbuf][kk][tr * 8]);
            float4 a1 = *reinterpret_cast<const float4*>(&As[cbuf][kk][tr * 8 + 4]);
            float a[8] = {a0.x, a0.y, a0.z, a0.w, a1.x, a1.y, a1.z, a1.w};
            float b[6];
#pragma unroll
            for (int j = 0; j < 6; j++) b[j] = Bs[cbuf][kk][tc * 6 + j];
#pragma unroll
            for (int i = 0; i < 8; i++)
#pragma unroll
                for (int j = 0; j < 6; j++) acc[i][j] += a[i] * b[j];
        }
        if (kt + 1 < 8) G2_STORE(cbuf ^ 1)
        __syncthreads();
    }

#pragma unroll
    for (int i = 0; i < 8; i++) {
        int gr = row0 + tr * 8 + i;
        if (gr < n) {
#pragma unroll
            for (int j = 0; j < 6; j++) {
                int col = tc * 6 + j;
                if (col < FOUT) g_H2[(size_t)gr * FOUT + col] = acc[i][j];
            }
        }
    }
#undef G2_LOAD
#undef G2_STORE
}

// ---------------- agg2 + bias + log_softmax ---------------------------------
__global__ __launch_bounds__(256) void k_agg2(
    const float* __restrict__ b2, float* __restrict__ out, int n)
{
    int gw = (blockIdx.x * blockDim.x + threadIdx.x) >> 5;
    int lane = threadIdx.x & 31;
    if (gw >= n) return;
    int i = gw;
    float di = g_dinv[i];
    bool v0 = lane < FOUT;
    bool v1 = (lane + 32) < FOUT;
    float a0 = v0 ? g_H2[(size_t)i * FOUT + lane]      * di * di : 0.f;
    float a1 = v1 ? g_H2[(size_t)i * FOUT + lane + 32] * di * di : 0.f;

    int beg = g_rowptr[i], end = g_rowptr[i + 1];
    for (int base = beg; base < end; base += 32) {
        int c = end - base; if (c > 32) c = 32;
        int s = 0; float w = 0.f;
        if (lane < c) { s = g_col[base + lane]; w = g_dinv[s] * di; }
        int k = 0;
        for (; k + 2 <= c; k += 2) {
            int   s0 = __shfl_sync(0xffffffffu, s, k);
            int   s1 = __shfl_sync(0xffffffffu, s, k + 1);
            float w0 = __shfl_sync(0xffffffffu, w, k);
            float w1 = __shfl_sync(0xffffffffu, w, k + 1);
            if (v0) a0 += g_H2[(size_t)s0 * FOUT + lane] * w0;
            if (v1) a1 += g_H2[(size_t)s0 * FOUT + lane + 32] * w0;
            if (v0) a0 += g_H2[(size_t)s1 * FOUT + lane] * w1;
            if (v1) a1 += g_H2[(size_t)s1 * FOUT + lane + 32] * w1;
        }
        for (; k < c; k++) {
            int   sk = __shfl_sync(0xffffffffu, s, k);
            float wk = __shfl_sync(0xffffffffu, w, k);
            if (v0) a0 += g_H2[(size_t)sk * FOUT + lane] * wk;
            if (v1) a1 += g_H2[(size_t)sk * FOUT + lane + 32] * wk;
        }
    }
    if (v0) a0 += b2[lane];
    if (v1) a1 += b2[lane + 32];

    float m = fmaxf(v0 ? a0 : -INFINITY, v1 ? a1 : -INFINITY);
#pragma unroll
    for (int off = 16; off; off >>= 1) m = fmaxf(m, __shfl_xor_sync(0xffffffffu, m, off));
    float e = (v0 ? expf(a0 - m) : 0.f) + (v1 ? expf(a1 - m) : 0.f);
#pragma unroll
    for (int off = 16; off; off >>= 1) e += __shfl_xor_sync(0xffffffffu, e, off);
    float ls = m + logf(e);
    if (v0) out[(size_t)i * FOUT + lane]      = a0 - ls;
    if (v1) out[(size_t)i * FOUT + lane + 32] = a1 - ls;
}

// ---------------- launch ----------------------------------------------------
extern "C" void kernel_launch(void* const* d_in, const int* in_sizes, int n_in,
                              void* d_out, int out_size)
{
    const float* x  = (const float*)d_in[0];
    const float* W1 = (const float*)d_in[1];
    const float* b1 = (const float*)d_in[2];
    const float* W2 = (const float*)d_in[3];
    const float* b2 = (const float*)d_in[4];
    const int*   ei = (const int*)d_in[5];   // int32 or int64; detected on device
    float* out = (float*)d_out;

    int n = in_sizes[0] / FIN;
    long long E = in_sizes[5] / 2;
    int nb = (n + 255) / 256;

    k_init<<<nb, 256>>>(ei, n);
    k_degree<<<(int)((E + 255) / 256), 256>>>(ei, E);
    k_part<<<nb, 256>>>(n);
    k_write<<<nb, 256>>>(n, nb);
    k_scatter<<<(int)((E + 255) / 256), 256>>>(ei, E);
    k_gemm1<<<(n + 127) / 128, 256>>>(x, W1, n);
    k_agg1<<<(n * 32 + 255) / 256, 256>>>(b1, n);
    k_gemm2<<<(n + 127) / 128, 128>>>(W2, n);
    k_agg2<<<(n * 32 + 255) / 256, 256>>>(b2, out, n);
}

// round 7
// speedup vs baseline: 3.2582x; 1.2532x over previous
#include <cuda_runtime.h>
#include <cuda_bf16.h>
#include <cuda_fp16.h>
#include <math.h>

// Problem constants (with headroom on N/E for safety)
#define FIN   500
#define FH    128
#define FOUT  47
#define NMAX  65536
#define EMAX  1048576

// ---------------- scratch (static device globals; no allocation) -------------
__device__ __align__(16) float g_dinv[NMAX];
__device__ int   g_cnt[NMAX];
__device__ int   g_rowptr[NMAX + 1];
__device__ int   g_wp[NMAX];
__device__ int   g_col[EMAX];
__device__ int   g_bsum[256];
__device__ __align__(16) unsigned g_H1bf[(size_t)NMAX * 64];   // x @ W1, bf16x2 packed
__device__ __align__(16) float g_H1r[(size_t)NMAX * FH];        // relu(agg1 + b1)
__device__ __align__(16) float g_H2 [(size_t)NMAX * FOUT];      // H1r @ W2
__device__ int   g_is64;

__device__ __forceinline__ int ld_edge(const int* p, long long idx, int is64) {
    return is64 ? p[2 * idx] : p[idx];
}

// ---------------- init: zero counters + dtype detect (fused) -----------------
// int64 LE: odd 32-bit words are 0 (values < 50000). int32: odd words random.
__global__ void k_init(const int* ei, int n) {
    int i = blockIdx.x * blockDim.x + threadIdx.x;
    if (i < n) g_cnt[i] = 0;
    if (blockIdx.x == 0 && threadIdx.x < 32) {
        int lane = threadIdx.x;
        int nz = (ei[2 * lane + 1] != 0) ? 1 : 0;
        unsigned b = __ballot_sync(0xffffffffu, nz);
        if (lane == 0) g_is64 = (b == 0u) ? 1 : 0;
    }
}

__global__ void k_degree(const int* ei, long long E) {
    long long e = (long long)blockIdx.x * blockDim.x + threadIdx.x;
    if (e >= E) return;
    int is64 = g_is64;
    int dst = ld_edge(ei, E + e, is64);
    atomicAdd(&g_cnt[dst], 1);
}

// ---------------- 2-phase parallel scan --------------------------------------
// phase 1: per-block (256 elems) reduction -> g_bsum
__global__ void k_part(int n) {
    __shared__ int sh[8];
    int t = threadIdx.x;
    int i = blockIdx.x * 256 + t;
    int v = (i < n) ? g_cnt[i] : 0;
#pragma unroll
    for (int off = 16; off; off >>= 1) v += __shfl_xor_sync(0xffffffffu, v, off);
    if ((t & 31) == 0) sh[t >> 5] = v;
    __syncthreads();
    if (t < 8) {
        int s = sh[t];
#pragma unroll
        for (int off = 4; off; off >>= 1) s += __shfl_xor_sync(0xffu, s, off);
        if (t == 0) g_bsum[blockIdx.x] = s;
    }
}

// phase 2: each block reduces preceding partials itself, then internal scan
__global__ void k_write(int n, int nb) {
    __shared__ int sh[256];
    __shared__ int red[8];
    int t = threadIdx.x;
    int b = blockIdx.x;

    int v = (t < b && t < nb) ? g_bsum[t] : 0;
#pragma unroll
    for (int off = 16; off; off >>= 1) v += __shfl_xor_sync(0xffffffffu, v, off);
    if ((t & 31) == 0) red[t >> 5] = v;
    __syncthreads();
    int boff;
    {
        int s = (t < 8) ? red[t] : 0;
        if (t < 8) {
#pragma unroll
            for (int off = 4; off; off >>= 1) s += __shfl_xor_sync(0xffu, s, off);
            if (t == 0) red[0] = s;
        }
        __syncthreads();
        boff = red[0];
    }

    int i = b * 256 + t;
    int c = (i < n) ? g_cnt[i] : 0;
    sh[t] = c;
    __syncthreads();
#pragma unroll
    for (int off = 1; off < 256; off <<= 1) {
        int u = (t >= off) ? sh[t - off] : 0;
        __syncthreads();
        sh[t] += u;
        __syncthreads();
    }
    if (i < n) {
        int pos = boff + sh[t] - c;
        g_rowptr[i] = pos;
        g_wp[i] = pos;
        g_dinv[i] = rsqrtf((float)(c + 1));   // +1 self-loop
    }
    if (b == nb - 1 && t == 255) g_rowptr[n] = boff + sh[255];
}

__global__ void k_scatter(const int* ei, long long E) {
    long long e = (long long)blockIdx.x * blockDim.x + threadIdx.x;
    if (e >= E) return;
    int is64 = g_is64;
    int src = ld_edge(ei, e, is64);
    int dst = ld_edge(ei, E + e, is64);
    int pos = atomicAdd(&g_wp[dst], 1);
    g_col[pos] = src;
}

// ---------------- mma helpers ------------------------------------------------
__device__ __forceinline__ void ldsm_x4(unsigned& r0, unsigned& r1, unsigned& r2, unsigned& r3,
                                        unsigned addr) {
    asm volatile("ldmatrix.sync.aligned.m8n8.x4.shared.b16 {%0,%1,%2,%3}, [%4];\n"
                 : "=r"(r0), "=r"(r1), "=r"(r2), "=r"(r3) : "r"(addr));
}
__device__ __forceinline__ void ldsm_x4_t(unsigned& r0, unsigned& r1, unsigned& r2, unsigned& r3,
                                          unsigned addr) {
    asm volatile("ldmatrix.sync.aligned.m8n8.x4.trans.shared.b16 {%0,%1,%2,%3}, [%4];\n"
                 : "=r"(r0), "=r"(r1), "=r"(r2), "=r"(r3) : "r"(addr));
}
__device__ __forceinline__ void mma_fp16(float* d, const unsigned* a, const unsigned* b) {
    asm volatile("mma.sync.aligned.m16n8k16.row.col.f32.f16.f16.f32 "
                 "{%0,%1,%2,%3}, {%4,%5,%6,%7}, {%8,%9}, {%0,%1,%2,%3};\n"
                 : "+f"(d[0]), "+f"(d[1]), "+f"(d[2]), "+f"(d[3])
                 : "r"(a[0]), "r"(a[1]), "r"(a[2]), "r"(a[3]), "r"(b[0]), "r"(b[1]));
}
// float4 -> 2x packed half2
__device__ __forceinline__ uint2 cvt4h(const float4 v) {
    __half2 h0 = __floats2half2_rn(v.x, v.y);
    __half2 h1 = __floats2half2_rn(v.z, v.w);
    uint2 r;
    r.x = *reinterpret_cast<unsigned*>(&h0);
    r.y = *reinterpret_cast<unsigned*>(&h1);
    return r;
}
__device__ __forceinline__ unsigned pack_bf16(float a, float b) {
    return ((unsigned)__bfloat16_as_ushort(__float2bfloat16(b)) << 16) |
           __bfloat16_as_ushort(__float2bfloat16(a));
}

// ---------------- GEMM1: H1 = x @ W1 via fp16 tensor cores -------------------
// 128x128 block tile, BK=16, K padded to 512 (32 chunks). 8 warps = 4m x 2n.
// Single fp16 MMA per fragment pair, fp32 accum. Output packed bf16x2.
#define G1_KT 32
#define A_LDS 24
#define B_LDS 136
__global__ __launch_bounds__(256) void k_gemm1(
    const float* __restrict__ x, const float* __restrict__ W, int n)
{
    __shared__ __align__(16) __half As[2][128][A_LDS];
    __shared__ __align__(16) __half Bs[2][16][B_LDS];

    int tid = threadIdx.x;
    int lane = tid & 31;
    int wid = tid >> 5;
    int wm = wid & 3;
    int wn = wid >> 2;
    int row0 = blockIdx.x * 128;

    float acc[2][8][4];
#pragma unroll
    for (int mi = 0; mi < 2; mi++)
#pragma unroll
        for (int ni = 0; ni < 8; ni++)
#pragma unroll
            for (int q = 0; q < 4; q++) acc[mi][ni][q] = 0.f;

    unsigned a_base = (unsigned)__cvta_generic_to_shared(&As[0][0][0]);
    unsigned b_base = (unsigned)__cvta_generic_to_shared(&Bs[0][0][0]);
    const unsigned A_BUF = 128 * A_LDS * 2;
    const unsigned B_BUF = 16 * B_LDS * 2;
    unsigned a_lane = ((lane & 15) * A_LDS + (lane >> 4) * 8) * 2;
    unsigned b_lane = ((lane & 15) * B_LDS + (lane >> 4) * 8) * 2;

    float4 a_ld[2], b_ld[2];

#define G1_LOAD(k0)                                                            \
    {                                                                          \
        _Pragma("unroll")                                                      \
        for (int u = 0; u < 2; u++) {                                          \
            int f4 = tid + u * 256;                                            \
            int a_row = f4 >> 2, grp = f4 & 3;                                 \
            int gk = (k0) + grp * 4;                                           \
            int gr = row0 + a_row;                                             \
            if (gr < n && gk + 4 <= FIN)                                       \
                a_ld[u] = *reinterpret_cast<const float4*>(&x[(size_t)gr * FIN + gk]); \
            else a_ld[u] = make_float4(0.f, 0.f, 0.f, 0.f);                    \
            int bk = f4 >> 5, bc4 = f4 & 31;                                   \
            int gkb = (k0) + bk;                                               \
            if (gkb < FIN)                                                     \
                b_ld[u] = *reinterpret_cast<const float4*>(&W[(size_t)gkb * FH + bc4 * 4]); \
            else b_ld[u] = make_float4(0.f, 0.f, 0.f, 0.f);                    \
        }                                                                      \
    }

#define G1_STORE(buf)                                                          \
    {                                                                          \
        _Pragma("unroll")                                                      \
        for (int u = 0; u < 2; u++) {                                          \
            int f4 = tid + u * 256;                                            \
            int a_row = f4 >> 2, grp = f4 & 3;                                 \
            *reinterpret_cast<uint2*>(&As[buf][a_row][grp * 4]) = cvt4h(a_ld[u]); \
            int bk = f4 >> 5, bc4 = f4 & 31;                                   \
            *reinterpret_cast<uint2*>(&Bs[buf][bk][bc4 * 4]) = cvt4h(b_ld[u]); \
        }                                                                      \
    }

    G1_LOAD(0)
    G1_STORE(0)
    __syncthreads();

    for (int kt = 0; kt < G1_KT; kt++) {
        int cbuf = kt & 1;
        if (kt + 1 < G1_KT) G1_LOAD((kt + 1) * 16)

        unsigned af[2][4], bf[8][2];
#pragma unroll
        for (int mi = 0; mi < 2; mi++) {
            unsigned roff = (unsigned)((wm * 32 + mi * 16) * A_LDS * 2);
            ldsm_x4(af[mi][0], af[mi][1], af[mi][2], af[mi][3],
                    a_base + cbuf * A_BUF + roff + a_lane);
        }
#pragma unroll
        for (int p = 0; p < 4; p++) {
            unsigned coff = (unsigned)((wn * 64 + p * 16) * 2);
            ldsm_x4_t(bf[2*p][0], bf[2*p][1], bf[2*p+1][0], bf[2*p+1][1],
                      b_base + cbuf * B_BUF + coff + b_lane);
        }

#pragma unroll
        for (int mi = 0; mi < 2; mi++)
#pragma unroll
            for (int ni = 0; ni < 8; ni++)
                mma_fp16(acc[mi][ni], af[mi], bf[ni]);

        if (kt + 1 < G1_KT) G1_STORE(cbuf ^ 1)
        __syncthreads();
    }

    // epilogue -> packed bf16x2. acc[..][0,1] = cols (c,c+1); [2,3] = row+8.
    int rbase = row0 + wm * 32 + (lane >> 2);
    int cbase = wn * 64 + (lane & 3) * 2;
#pragma unroll
    for (int mi = 0; mi < 2; mi++) {
#pragma unroll
        for (int ni = 0; ni < 8; ni++) {
            int col = cbase + ni * 8;      // even
            int r0 = rbase + mi * 16;
            if (r0 < n)
                g_H1bf[(size_t)r0 * 64 + (col >> 1)] =
                    pack_bf16(acc[mi][ni][0], acc[mi][ni][1]);
            if (r0 + 8 < n)
                g_H1bf[(size_t)(r0 + 8) * 64 + (col >> 1)] =
                    pack_bf16(acc[mi][ni][2], acc[mi][ni][3]);
        }
    }
#undef G1_LOAD
#undef G1_STORE
}

// ---------------- agg1: H1r = relu( Ahat @ H1 + b1 ) ------------------------
// One warp per node; lane covers 4 features (uint2 of bf16x2). 256B/row gathers.
__device__ __forceinline__ void bf2_fma(float4& acc, uint2 u, float w) {
    float f0 = __uint_as_float(u.x << 16);
    float f1 = __uint_as_float(u.x & 0xffff0000u);
    float f2 = __uint_as_float(u.y << 16);
    float f3 = __uint_as_float(u.y & 0xffff0000u);
    acc.x += f0 * w; acc.y += f1 * w; acc.z += f2 * w; acc.w += f3 * w;
}
__global__ __launch_bounds__(256) void k_agg1(const float* __restrict__ b1, int n) {
    int gw = (blockIdx.x * blockDim.x + threadIdx.x) >> 5;
    int lane = threadIdx.x & 31;
    if (gw >= n) return;
    int i = gw;
    float di = g_dinv[i];
    const uint2* H = reinterpret_cast<const uint2*>(g_H1bf);
    float4 acc = make_float4(0.f, 0.f, 0.f, 0.f);
    bf2_fma(acc, H[(size_t)i * 32 + lane], di * di);   // self loop

    int beg = g_rowptr[i], end = g_rowptr[i + 1];
    for (int base = beg; base < end; base += 32) {
        int c = end - base; if (c > 32) c = 32;
        int s = 0; float w = 0.f;
        if (lane < c) { s = g_col[base + lane]; w = g_dinv[s] * di; }
        int k = 0;
        for (; k + 4 <= c; k += 4) {
            int   s0 = __shfl_sync(0xffffffffu, s, k);
            int   s1 = __shfl_sync(0xffffffffu, s, k + 1);
            int   s2 = __shfl_sync(0xffffffffu, s, k + 2);
            int   s3 = __shfl_sync(0xffffffffu, s, k + 3);
            float w0 = __shfl_sync(0xffffffffu, w, k);
            float w1 = __shfl_sync(0xffffffffu, w, k + 1);
            float w2 = __shfl_sync(0xffffffffu, w, k + 2);
            float w3 = __shfl_sync(0xffffffffu, w, k + 3);
            uint2 v0 = H[(size_t)s0 * 32 + lane];
            uint2 v1 = H[(size_t)s1 * 32 + lane];
            uint2 v2 = H[(size_t)s2 * 32 + lane];
            uint2 v3 = H[(size_t)s3 * 32 + lane];
            bf2_fma(acc, v0, w0);
            bf2_fma(acc, v1, w1);
            bf2_fma(acc, v2, w2);
            bf2_fma(acc, v3, w3);
        }
        for (; k < c; k++) {
            int   sk = __shfl_sync(0xffffffffu, s, k);
            float wk = __shfl_sync(0xffffffffu, w, k);
            bf2_fma(acc, H[(size_t)sk * 32 + lane], wk);
        }
    }
    float4 b = reinterpret_cast<const float4*>(b1)[lane];
    float4 o = make_float4(fmaxf(acc.x + b.x, 0.f), fmaxf(acc.y + b.y, 0.f),
                           fmaxf(acc.z + b.z, 0.f), fmaxf(acc.w + b.w, 0.f));
    reinterpret_cast<float4*>(g_H1r)[(size_t)i * 32 + lane] = o;
}

// ---------------- GEMM2: H2 = H1r @ W2  (n x 128) @ (128 x 47) --------------
__global__ __launch_bounds__(128, 4) void k_gemm2(const float* __restrict__ W2, int n) {
    __shared__ __align__(16) float As[2][16][132];
    __shared__ __align__(16) float Bs[2][16][48];

    int tid = threadIdx.x;
    int row0 = blockIdx.x * 128;
    int tr = tid >> 3;
    int tc = tid & 7;

    float acc[8][6];
#pragma unroll
    for (int i = 0; i < 8; i++)
#pragma unroll
        for (int j = 0; j < 6; j++) acc[i][j] = 0.f;

    float4 a_ld[4];
    float  b_ld[6];

#define G2_LOAD(k0)                                                            \
    {                                                                          \
        _Pragma("unroll")                                                      \
        for (int u = 0; u < 4; u++) {                                          \
            int f4 = tid + u * 128;                                            \
            int a_row = f4 >> 2, grp = f4 & 3;                                 \
            int gr = row0 + a_row;                                             \
            a_ld[u] = (gr < n)                                                 \
                ? *reinterpret_cast<const float4*>(&g_H1r[(size_t)gr * FH + (k0) + grp * 4]) \
                : make_float4(0.f, 0.f, 0.f, 0.f);                             \
        }                                                                      \
        _Pragma("unroll")                                                      \
        for (int u = 0; u < 6; u++) {                                          \
            int idx = tid + u * 128;                                           \
            int bk = idx / 48, bc = idx - bk * 48;                             \
            b_ld[u] = (bc < FOUT) ? W2[(size_t)((k0) + bk) * FOUT + bc] : 0.f; \
        }                                                                      \
    }

#define G2_STORE(buf)                                                          \
    {                                                                          \
        _Pragma("unroll")                                                      \
        for (int u = 0; u < 4; u++) {                                          \
            int f4 = tid + u * 128;                                            \
            int a_row = f4 >> 2, grp = f4 & 3;                                 \
            As[buf][grp * 4 + 0][a_row] = a_ld[u].x;                           \
            As[buf][grp * 4 + 1][a_row] = a_ld[u].y;                           \
            As[buf][grp * 4 + 2][a_row] = a_ld[u].z;                           \
            As[buf][grp * 4 + 3][a_row] = a_ld[u].w;                           \
        }                                                                      \
        _Pragma("unroll")                                                      \
        for (int u = 0; u < 6; u++) {                                          \
            int idx = tid + u * 128;                                           \
            int bk = idx / 48, bc = idx - bk * 48;                             \
            Bs[buf][bk][bc] = b_ld[u];                                         \
        }                                                                      \
    }

    G2_LOAD(0)
    G2_STORE(0)
    __syncthreads();

    for (int kt = 0; kt < 8; kt++) {
        int cbuf = kt & 1;
        if (kt + 1 < 8) G2_LOAD((kt + 1) * 16)
#pragma unroll
        for (int kk = 0; kk < 16; kk++) {
            float4 a0 = *reinterpret_cast<const float4*>(&As[cbuf][kk][tr * 8]);
            float4 a1 = *reinterpret_cast<const float4*>(&As[cbuf][kk][tr * 8 + 4]);
            float a[8] = {a0.x, a0.y, a0.z, a0.w, a1.x, a1.y, a1.z, a1.w};
            float b[6];
#pragma unroll
            for (int j = 0; j < 6; j++) b[j] = Bs[cbuf][kk][tc * 6 + j];
#pragma unroll
            for (int i = 0; i < 8; i++)
#pragma unroll
                for (int j = 0; j < 6; j++) acc[i][j] += a[i] * b[j];
        }
        if (kt + 1 < 8) G2_STORE(cbuf ^ 1)
        __syncthreads();
    }

#pragma unroll
    for (int i = 0; i < 8; i++) {
        int gr = row0 + tr * 8 + i;
        if (gr < n) {
#pragma unroll
            for (int j = 0; j < 6; j++) {
                int col = tc * 6 + j;
                if (col < FOUT) g_H2[(size_t)gr * FOUT + col] = acc[i][j];
            }
        }
    }
#undef G2_LOAD
#undef G2_STORE
}

// ---------------- agg2 + bias + log_softmax ---------------------------------
__global__ __launch_bounds__(256) void k_agg2(
    const float* __restrict__ b2, float* __restrict__ out, int n)
{
    int gw = (blockIdx.x * blockDim.x + threadIdx.x) >> 5;
    int lane = threadIdx.x & 31;
    if (gw >= n) return;
    int i = gw;
    float di = g_dinv[i];
    bool v0 = lane < FOUT;
    bool v1 = (lane + 32) < FOUT;
    float a0 = v0 ? g_H2[(size_t)i * FOUT + lane]      * di * di : 0.f;
    float a1 = v1 ? g_H2[(size_t)i * FOUT + lane + 32] * di * di : 0.f;

    int beg = g_rowptr[i], end = g_rowptr[i + 1];
    for (int base = beg; base < end; base += 32) {
        int c = end - base; if (c > 32) c = 32;
        int s = 0; float w = 0.f;
        if (lane < c) { s = g_col[base + lane]; w = g_dinv[s] * di; }
        int k = 0;
        for (; k + 2 <= c; k += 2) {
            int   s0 = __shfl_sync(0xffffffffu, s, k);
            int   s1 = __shfl_sync(0xffffffffu, s, k + 1);
            float w0 = __shfl_sync(0xffffffffu, w, k);
            float w1 = __shfl_sync(0xffffffffu, w, k + 1);
            if (v0) a0 += g_H2[(size_t)s0 * FOUT + lane] * w0;
            if (v1) a1 += g_H2[(size_t)s0 * FOUT + lane + 32] * w0;
            if (v0) a0 += g_H2[(size_t)s1 * FOUT + lane] * w1;
            if (v1) a1 += g_H2[(size_t)s1 * FOUT + lane + 32] * w1;
        }
        for (; k < c; k++) {
            int   sk = __shfl_sync(0xffffffffu, s, k);
            float wk = __shfl_sync(0xffffffffu, w, k);
            if (v0) a0 += g_H2[(size_t)sk * FOUT + lane] * wk;
            if (v1) a1 += g_H2[(size_t)sk * FOUT + lane + 32] * wk;
        }
    }
    if (v0) a0 += b2[lane];
    if (v1) a1 += b2[lane + 32];

    float m = fmaxf(v0 ? a0 : -INFINITY, v1 ? a1 : -INFINITY);
#pragma unroll
    for (int off = 16; off; off >>= 1) m = fmaxf(m, __shfl_xor_sync(0xffffffffu, m, off));
    float e = (v0 ? expf(a0 - m) : 0.f) + (v1 ? expf(a1 - m) : 0.f);
#pragma unroll
    for (int off = 16; off; off >>= 1) e += __shfl_xor_sync(0xffffffffu, e, off);
    float ls = m + logf(e);
    if (v0) out[(size_t)i * FOUT + lane]      = a0 - ls;
    if (v1) out[(size_t)i * FOUT + lane + 32] = a1 - ls;
}

// ---------------- launch ----------------------------------------------------
extern "C" void kernel_launch(void* const* d_in, const int* in_sizes, int n_in,
                              void* d_out, int out_size)
{
    const float* x  = (const float*)d_in[0];
    const float* W1 = (const float*)d_in[1];
    const float* b1 = (const float*)d_in[2];
    const float* W2 = (const float*)d_in[3];
    const float* b2 = (const float*)d_in[4];
    const int*   ei = (const int*)d_in[5];   // int32 or int64; detected on device
    float* out = (float*)d_out;

    int n = in_sizes[0] / FIN;
    long long E = in_sizes[5] / 2;
    int nb = (n + 255) / 256;

    k_init<<<nb, 256>>>(ei, n);
    k_degree<<<(int)((E + 255) / 256), 256>>>(ei, E);
    k_part<<<nb, 256>>>(n);
    k_write<<<nb, 256>>>(n, nb);
    k_scatter<<<(int)((E + 255) / 256), 256>>>(ei, E);
    k_gemm1<<<(n + 127) / 128, 256>>>(x, W1, n);
    k_agg1<<<(n * 32 + 255) / 256, 256>>>(b1, n);
    k_gemm2<<<(n + 127) / 128, 128>>>(W2, n);
    k_agg2<<<(n * 32 + 255) / 256, 256>>>(b2, out, n);
}

// round 11
// speedup vs baseline: 3.4942x; 1.0724x over previous
#include <cuda_runtime.h>
#include <cuda_bf16.h>
#include <cuda_fp16.h>
#include <math.h>

// Problem constants (with headroom on N/E for safety)
#define FIN   500
#define FH    128
#define FOUT  47
#define NMAX  65536
#define EMAX  1048576

// ---------------- scratch (static device globals; no allocation) -------------
__device__ __align__(16) float g_dinv[NMAX];
__device__ int   g_cnt[NMAX];
__device__ int   g_rowptr[NMAX + 1];
__device__ int   g_wp[NMAX];
__device__ int   g_col[EMAX];
__device__ int   g_bsum[256];
__device__ __align__(16) unsigned g_H1bf [(size_t)NMAX * 64];  // x @ W1, bf16x2
__device__ __align__(16) unsigned g_H1rbf[(size_t)NMAX * 64];  // relu(agg1+b1), bf16x2
__device__ __align__(16) unsigned g_H2bf [(size_t)NMAX * 32];  // H1r @ W2, bf16x2, 64-col pad
__device__ __align__(16) unsigned g_W2bf [128 * 32];           // W2 bf16x2, 64-col pad
__device__ int   g_is64;

__device__ __forceinline__ int ld_edge(const int* p, long long idx, int is64) {
    return is64 ? p[2 * idx] : p[idx];
}
__device__ __forceinline__ unsigned pack_bf16(float a, float b) {
    return ((unsigned)__bfloat16_as_ushort(__float2bfloat16(b)) << 16) |
           __bfloat16_as_ushort(__float2bfloat16(a));
}

// ---------------- init: zero counters + dtype detect + W2 pack ---------------
// int64 LE: odd 32-bit words are 0 (values < 50000). int32: odd words random.
__global__ void k_init(const int* ei, const float* W2, int n) {
    int i = blockIdx.x * blockDim.x + threadIdx.x;
    if (i < n) g_cnt[i] = 0;
    if (blockIdx.x == 0 && threadIdx.x < 32) {
        int lane = threadIdx.x;
        int nz = (ei[2 * lane + 1] != 0) ? 1 : 0;
        unsigned b = __ballot_sync(0xffffffffu, nz);
        if (lane == 0) g_is64 = (b == 0u) ? 1 : 0;
    }
    if (blockIdx.x == 1) {
        for (int idx = threadIdx.x; idx < 128 * 32; idx += blockDim.x) {
            int k = idx >> 5, c2 = idx & 31;
            float f0 = (2 * c2     < FOUT) ? W2[k * FOUT + 2 * c2]     : 0.f;
            float f1 = (2 * c2 + 1 < FOUT) ? W2[k * FOUT + 2 * c2 + 1] : 0.f;
            g_W2bf[idx] = pack_bf16(f0, f1);
        }
    }
}

__global__ void k_degree(const int* ei, long long E) {
    long long e = (long long)blockIdx.x * blockDim.x + threadIdx.x;
    if (e >= E) return;
    int is64 = g_is64;
    int dst = ld_edge(ei, E + e, is64);
    atomicAdd(&g_cnt[dst], 1);
}

// ---------------- 2-phase parallel scan --------------------------------------
__global__ void k_part(int n) {
    __shared__ int sh[8];
    int t = threadIdx.x;
    int i = blockIdx.x * 256 + t;
    int v = (i < n) ? g_cnt[i] : 0;
#pragma unroll
    for (int off = 16; off; off >>= 1) v += __shfl_xor_sync(0xffffffffu, v, off);
    if ((t & 31) == 0) sh[t >> 5] = v;
    __syncthreads();
    if (t < 8) {
        int s = sh[t];
#pragma unroll
        for (int off = 4; off; off >>= 1) s += __shfl_xor_sync(0xffu, s, off);
        if (t == 0) g_bsum[blockIdx.x] = s;
    }
}

__global__ void k_write(int n, int nb) {
    __shared__ int sh[256];
    __shared__ int red[8];
    int t = threadIdx.x;
    int b = blockIdx.x;

    int v = (t < b && t < nb) ? g_bsum[t] : 0;
#pragma unroll
    for (int off = 16; off; off >>= 1) v += __shfl_xor_sync(0xffffffffu, v, off);
    if ((t & 31) == 0) red[t >> 5] = v;
    __syncthreads();
    int boff;
    {
        int s = (t < 8) ? red[t] : 0;
        if (t < 8) {
#pragma unroll
            for (int off = 4; off; off >>= 1) s += __shfl_xor_sync(0xffu, s, off);
            if (t == 0) red[0] = s;
        }
        __syncthreads();
        boff = red[0];
    }

    int i = b * 256 + t;
    int c = (i < n) ? g_cnt[i] : 0;
    sh[t] = c;
    __syncthreads();
#pragma unroll
    for (int off = 1; off < 256; off <<= 1) {
        int u = (t >= off) ? sh[t - off] : 0;
        __syncthreads();
        sh[t] += u;
        __syncthreads();
    }
    if (i < n) {
        int pos = boff + sh[t] - c;
        g_rowptr[i] = pos;
        g_wp[i] = pos;
        g_dinv[i] = rsqrtf((float)(c + 1));   // +1 self-loop
    }
    if (b == nb - 1 && t == 255) g_rowptr[n] = boff + sh[255];
}

__global__ void k_scatter(const int* ei, long long E) {
    long long e = (long long)blockIdx.x * blockDim.x + threadIdx.x;
    if (e >= E) return;
    int is64 = g_is64;
    int src = ld_edge(ei, e, is64);
    int dst = ld_edge(ei, E + e, is64);
    int pos = atomicAdd(&g_wp[dst], 1);
    g_col[pos] = src;
}

// ---------------- mma helpers ------------------------------------------------
__device__ __forceinline__ void ldsm_x4(unsigned& r0, unsigned& r1, unsigned& r2, unsigned& r3,
                                        unsigned addr) {
    asm volatile("ldmatrix.sync.aligned.m8n8.x4.shared.b16 {%0,%1,%2,%3}, [%4];\n"
                 : "=r"(r0), "=r"(r1), "=r"(r2), "=r"(r3) : "r"(addr));
}
__device__ __forceinline__ void ldsm_x4_t(unsigned& r0, unsigned& r1, unsigned& r2, unsigned& r3,
                                          unsigned addr) {
    asm volatile("ldmatrix.sync.aligned.m8n8.x4.trans.shared.b16 {%0,%1,%2,%3}, [%4];\n"
                 : "=r"(r0), "=r"(r1), "=r"(r2), "=r"(r3) : "r"(addr));
}
__device__ __forceinline__ void mma_fp16(float* d, const unsigned* a, const unsigned* b) {
    asm volatile("mma.sync.aligned.m16n8k16.row.col.f32.f16.f16.f32 "
                 "{%0,%1,%2,%3}, {%4,%5,%6,%7}, {%8,%9}, {%0,%1,%2,%3};\n"
                 : "+f"(d[0]), "+f"(d[1]), "+f"(d[2]), "+f"(d[3])
                 : "r"(a[0]), "r"(a[1]), "r"(a[2]), "r"(a[3]), "r"(b[0]), "r"(b[1]));
}
__device__ __forceinline__ void mma_bf16(float* d, const unsigned* a, const unsigned* b) {
    asm volatile("mma.sync.aligned.m16n8k16.row.col.f32.bf16.bf16.f32 "
                 "{%0,%1,%2,%3}, {%4,%5,%6,%7}, {%8,%9}, {%0,%1,%2,%3};\n"
                 : "+f"(d[0]), "+f"(d[1]), "+f"(d[2]), "+f"(d[3])
                 : "r"(a[0]), "r"(a[1]), "r"(a[2]), "r"(a[3]), "r"(b[0]), "r"(b[1]));
}
// float4 -> 2x packed half2
__device__ __forceinline__ uint2 cvt4h(const float4 v) {
    __half2 h0 = __floats2half2_rn(v.x, v.y);
    __half2 h1 = __floats2half2_rn(v.z, v.w);
    uint2 r;
    r.x = *reinterpret_cast<unsigned*>(&h0);
    r.y = *reinterpret_cast<unsigned*>(&h1);
    return r;
}

// ---------------- GEMM1: H1 = x @ W1 via fp16 tensor cores -------------------
// 128x128 block tile, BK=16, K padded to 512 (32 chunks). 8 warps = 4m x 2n.
#define G1_KT 32
#define A_LDS 24
#define B_LDS 136
__global__ __launch_bounds__(256) void k_gemm1(
    const float* __restrict__ x, const float* __restrict__ W, int n)
{
    __shared__ __align__(16) __half As[2][128][A_LDS];
    __shared__ __align__(16) __half Bs[2][16][B_LDS];

    int tid = threadIdx.x;
    int lane = tid & 31;
    int wid = tid >> 5;
    int wm = wid & 3;
    int wn = wid >> 2;
    int row0 = blockIdx.x * 128;

    float acc[2][8][4];
#pragma unroll
    for (int mi = 0; mi < 2; mi++)
#pragma unroll
        for (int ni = 0; ni < 8; ni++)
#pragma unroll
            for (int q = 0; q < 4; q++) acc[mi][ni][q] = 0.f;

    unsigned a_base = (unsigned)__cvta_generic_to_shared(&As[0][0][0]);
    unsigned b_base = (unsigned)__cvta_generic_to_shared(&Bs[0][0][0]);
    const unsigned A_BUF = 128 * A_LDS * 2;
    const unsigned B_BUF = 16 * B_LDS * 2;
    unsigned a_lane = ((lane & 15) * A_LDS + (lane >> 4) * 8) * 2;
    unsigned b_lane = ((lane & 15) * B_LDS + (lane >> 4) * 8) * 2;

    float4 a_ld[2], b_ld[2];

#define G1_LOAD(k0)                                                            \
    {                                                                          \
        _Pragma("unroll")                                                      \
        for (int u = 0; u < 2; u++) {                                          \
            int f4 = tid + u * 256;                                            \
            int a_row = f4 >> 2, grp = f4 & 3;                                 \
            int gk = (k0) + grp * 4;                                           \
            int gr = row0 + a_row;                                             \
            if (gr < n && gk + 4 <= FIN)                                       \
                a_ld[u] = *reinterpret_cast<const float4*>(&x[(size_t)gr * FIN + gk]); \
            else a_ld[u] = make_float4(0.f, 0.f, 0.f, 0.f);                    \
            int bk = f4 >> 5, bc4 = f4 & 31;                                   \
            int gkb = (k0) + bk;                                               \
            if (gkb < FIN)                                                     \
                b_ld[u] = *reinterpret_cast<const float4*>(&W[(size_t)gkb * FH + bc4 * 4]); \
            else b_ld[u] = make_float4(0.f, 0.f, 0.f, 0.f);                    \
        }                                                                      \
    }

#define G1_STORE(buf)                                                          \
    {                                                                          \
        _Pragma("unroll")                                                      \
        for (int u = 0; u < 2; u++) {                                          \
            int f4 = tid + u * 256;                                            \
            int a_row = f4 >> 2, grp = f4 & 3;                                 \
            *reinterpret_cast<uint2*>(&As[buf][a_row][grp * 4]) = cvt4h(a_ld[u]); \
            int bk = f4 >> 5, bc4 = f4 & 31;                                   \
            *reinterpret_cast<uint2*>(&Bs[buf][bk][bc4 * 4]) = cvt4h(b_ld[u]); \
        }                                                                      \
    }

    G1_LOAD(0)
    G1_STORE(0)
    __syncthreads();

    for (int kt = 0; kt < G1_KT; kt++) {
        int cbuf = kt & 1;
        if (kt + 1 < G1_KT) G1_LOAD((kt + 1) * 16)

        unsigned af[2][4], bfr[8][2];
#pragma unroll
        for (int mi = 0; mi < 2; mi++) {
            unsigned roff = (unsigned)((wm * 32 + mi * 16) * A_LDS * 2);
            ldsm_x4(af[mi][0], af[mi][1], af[mi][2], af[mi][3],
                    a_base + cbuf * A_BUF + roff + a_lane);
        }
#pragma unroll
        for (int p = 0; p < 4; p++) {
            unsigned coff = (unsigned)((wn * 64 + p * 16) * 2);
            ldsm_x4_t(bfr[2*p][0], bfr[2*p][1], bfr[2*p+1][0], bfr[2*p+1][1],
                      b_base + cbuf * B_BUF + coff + b_lane);
        }

#pragma unroll
        for (int mi = 0; mi < 2; mi++)
#pragma unroll
            for (int ni = 0; ni < 8; ni++)
                mma_fp16(acc[mi][ni], af[mi], bfr[ni]);

        if (kt + 1 < G1_KT) G1_STORE(cbuf ^ 1)
        __syncthreads();
    }

    int rbase = row0 + wm * 32 + (lane >> 2);
    int cbase = wn * 64 + (lane & 3) * 2;
#pragma unroll
    for (int mi = 0; mi < 2; mi++) {
#pragma unroll
        for (int ni = 0; ni < 8; ni++) {
            int col = cbase + ni * 8;      // even
            int r0 = rbase + mi * 16;
            if (r0 < n)
                g_H1bf[(size_t)r0 * 64 + (col >> 1)] =
                    pack_bf16(acc[mi][ni][0], acc[mi][ni][1]);
            if (r0 + 8 < n)
                g_H1bf[(size_t)(r0 + 8) * 64 + (col >> 1)] =
                    pack_bf16(acc[mi][ni][2], acc[mi][ni][3]);
        }
    }
#undef G1_LOAD
#undef G1_STORE
}

// ---------------- agg1: H1r = relu( Ahat @ H1 + b1 ), bf16 out ---------------
__device__ __forceinline__ void bf2_fma(float4& acc, uint2 u, float w) {
    float f0 = __uint_as_float(u.x << 16);
    float f1 = __uint_as_float(u.x & 0xffff0000u);
    float f2 = __uint_as_float(u.y << 16);
    float f3 = __uint_as_float(u.y & 0xffff0000u);
    acc.x += f0 * w; acc.y += f1 * w; acc.z += f2 * w; acc.w += f3 * w;
}
__global__ __launch_bounds__(256) void k_agg1(const float* __restrict__ b1, int n) {
    int gw = (blockIdx.x * blockDim.x + threadIdx.x) >> 5;
    int lane = threadIdx.x & 31;
    if (gw >= n) return;
    int i = gw;
    float di = g_dinv[i];
    const uint2* H = reinterpret_cast<const uint2*>(g_H1bf);
    float4 acc = make_float4(0.f, 0.f, 0.f, 0.f);
    bf2_fma(acc, H[(size_t)i * 32 + lane], di * di);   // self loop

    int beg = g_rowptr[i], end = g_rowptr[i + 1];
    for (int base = beg; base < end; base += 32) {
        int c = end - base; if (c > 32) c = 32;
        int s = 0; float w = 0.f;
        if (lane < c) { s = g_col[base + lane]; w = g_dinv[s] * di; }
        int k = 0;
        for (; k + 4 <= c; k += 4) {
            int   s0 = __shfl_sync(0xffffffffu, s, k);
            int   s1 = __shfl_sync(0xffffffffu, s, k + 1);
            int   s2 = __shfl_sync(0xffffffffu, s, k + 2);
            int   s3 = __shfl_sync(0xffffffffu, s, k + 3);
            float w0 = __shfl_sync(0xffffffffu, w, k);
            float w1 = __shfl_sync(0xffffffffu, w, k + 1);
            float w2 = __shfl_sync(0xffffffffu, w, k + 2);
            float w3 = __shfl_sync(0xffffffffu, w, k + 3);
            uint2 v0 = H[(size_t)s0 * 32 + lane];
            uint2 v1 = H[(size_t)s1 * 32 + lane];
            uint2 v2 = H[(size_t)s2 * 32 + lane];
            uint2 v3 = H[(size_t)s3 * 32 + lane];
            bf2_fma(acc, v0, w0);
            bf2_fma(acc, v1, w1);
            bf2_fma(acc, v2, w2);
            bf2_fma(acc, v3, w3);
        }
        for (; k < c; k++) {
            int   sk = __shfl_sync(0xffffffffu, s, k);
            float wk = __shfl_sync(0xffffffffu, w, k);
            bf2_fma(acc, H[(size_t)sk * 32 + lane], wk);
        }
    }
    float4 b = reinterpret_cast<const float4*>(b1)[lane];
    uint2 o;
    o.x = pack_bf16(fmaxf(acc.x + b.x, 0.f), fmaxf(acc.y + b.y, 0.f));
    o.y = pack_bf16(fmaxf(acc.z + b.z, 0.f), fmaxf(acc.w + b.w, 0.f));
    reinterpret_cast<uint2*>(g_H1rbf)[(size_t)i * 32 + lane] = o;
}

// ---------------- GEMM2: H2 = H1r @ W2 via bf16 tensor cores -----------------
// 64x64 block tile, K=128 resident in smem (no k-chunking). 8 warps = 2m x 4n.
// A from bf16 H1r (no conversion), B from pre-packed g_W2bf. Output bf16 packed.
#define G2_ALD 136   // bf16 per A row (128 + 8 pad)
#define G2_BLD 72    // bf16 per B row (64 + 8 pad)
__global__ __launch_bounds__(256) void k_gemm2(int n) {
    __shared__ __align__(16) __nv_bfloat16 As[64][G2_ALD];
    __shared__ __align__(16) __nv_bfloat16 Bs[128][G2_BLD];

    int tid = threadIdx.x;
    int lane = tid & 31;
    int wid = tid >> 5;
    int wm = wid & 1;    // 2 warps along m, 32 rows each
    int wn = wid >> 1;   // 4 warps along n, 16 cols each
    int row0 = blockIdx.x * 64;

    // load A: 64 rows x 16 uint4 (256B/row)
    const uint4* H1 = reinterpret_cast<const uint4*>(g_H1rbf);
#pragma unroll
    for (int u = 0; u < 4; u++) {
        int f = tid + u * 256;
        int r = f >> 4, seg = f & 15;
        int gr = row0 + r;
        uint4 v = make_uint4(0u, 0u, 0u, 0u);
        if (gr < n) v = H1[(size_t)gr * 16 + seg];
        *reinterpret_cast<uint4*>(&As[r][seg * 8]) = v;
    }
    // load B: 128 rows x 8 uint4 (128B/row)
    const uint4* Wb = reinterpret_cast<const uint4*>(g_W2bf);
#pragma unroll
    for (int u = 0; u < 4; u++) {
        int f = tid + u * 256;
        int k = f >> 3, seg = f & 7;
        *reinterpret_cast<uint4*>(&Bs[k][seg * 8]) = Wb[f];
    }
    __syncthreads();

    float acc[2][2][4];
#pragma unroll
    for (int mi = 0; mi < 2; mi++)
#pragma unroll
        for (int ni = 0; ni < 2; ni++)
#pragma unroll
            for (int q = 0; q < 4; q++) acc[mi][ni][q] = 0.f;

    unsigned a_base = (unsigned)__cvta_generic_to_shared(&As[0][0]);
    unsigned b_base = (unsigned)__cvta_generic_to_shared(&Bs[0][0]);

#pragma unroll
    for (int k = 0; k < 8; k++) {
        unsigned af[2][4], bfr[2][2];
#pragma unroll
        for (int mi = 0; mi < 2; mi++) {
            unsigned addr = a_base +
                (unsigned)(((wm * 32 + mi * 16 + (lane & 15)) * G2_ALD +
                            k * 16 + (lane >> 4) * 8) * 2);
            ldsm_x4(af[mi][0], af[mi][1], af[mi][2], af[mi][3], addr);
        }
        unsigned baddr = b_base +
            (unsigned)(((k * 16 + (lane & 15)) * G2_BLD +
                        wn * 16 + (lane >> 4) * 8) * 2);
        ldsm_x4_t(bfr[0][0], bfr[0][1], bfr[1][0], bfr[1][1], baddr);
#pragma unroll
        for (int mi = 0; mi < 2; mi++)
#pragma unroll
            for (int ni = 0; ni < 2; ni++)
                mma_bf16(acc[mi][ni], af[mi], bfr[ni]);
    }

    int r_ = wm * 32 + (lane >> 2);
    int c0 = wn * 16 + (lane & 3) * 2;   // even
#pragma unroll
    for (int mi = 0; mi < 2; mi++) {
#pragma unroll
        for (int ni = 0; ni < 2; ni++) {
            int row = row0 + r_ + mi * 16;
            int col = c0 + ni * 8;
            if (row < n)
                g_H2bf[(size_t)row * 32 + (col >> 1)] =
                    pack_bf16(acc[mi][ni][0], acc[mi][ni][1]);
            if (row + 8 < n)
                g_H2bf[(size_t)(row + 8) * 32 + (col >> 1)] =
                    pack_bf16(acc[mi][ni][2], acc[mi][ni][3]);
        }
    }
}

// ---------------- agg2 + bias + log_softmax (bf16 gathers) -------------------
// One warp per node; lane owns one packed uint (features 2l, 2l+1).
// Each neighbor gather = one coalesced 128B line.
__global__ __launch_bounds__(256) void k_agg2(
    const float* __restrict__ b2, float* __restrict__ out, int n)
{
    int gw = (blockIdx.x * blockDim.x + threadIdx.x) >> 5;
    int lane = threadIdx.x & 31;
    if (gw >= n) return;
    int i = gw;
    float di = g_dinv[i];
    float sw = di * di;
    const unsigned* H = g_H2bf;
    unsigned u0 = H[(size_t)i * 32 + lane];
    float ax = __uint_as_float(u0 << 16) * sw;
    float ay = __uint_as_float(u0 & 0xffff0000u) * sw;

    int beg = g_rowptr[i], end = g_rowptr[i + 1];
    for (int base = beg; base < end; base += 32) {
        int c = end - base; if (c > 32) c = 32;
        int s = 0; float w = 0.f;
        if (lane < c) { s = g_col[base + lane]; w = g_dinv[s] * di; }
        int k = 0;
        for (; k + 4 <= c; k += 4) {
            int   s0 = __shfl_sync(0xffffffffu, s, k);
            int   s1 = __shfl_sync(0xffffffffu, s, k + 1);
            int   s2 = __shfl_sync(0xffffffffu, s, k + 2);
            int   s3 = __shfl_sync(0xffffffffu, s, k + 3);
            float w0 = __shfl_sync(0xffffffffu, w, k);
            float w1 = __shfl_sync(0xffffffffu, w, k + 1);
            float w2 = __shfl_sync(0xffffffffu, w, k + 2);
            float w3 = __shfl_sync(0xffffffffu, w, k + 3);
            unsigned v0 = H[(size_t)s0 * 32 + lane];
            unsigned v1 = H[(size_t)s1 * 32 + lane];
            unsigned v2 = H[(size_t)s2 * 32 + lane];
            unsigned v3 = H[(size_t)s3 * 32 + lane];
            ax += __uint_as_float(v0 << 16) * w0; ay += __uint_as_float(v0 & 0xffff0000u) * w0;
            ax += __uint_as_float(v1 << 16) * w1; ay += __uint_as_float(v1 & 0xffff0000u) * w1;
            ax += __uint_as_float(v2 << 16) * w2; ay += __uint_as_float(v2 & 0xffff0000u) * w2;
            ax += __uint_as_float(v3 << 16) * w3; ay += __uint_as_float(v3 & 0xffff0000u) * w3;
        }
        for (; k < c; k++) {
            int   sk = __shfl_sync(0xffffffffu, s, k);
            float wk = __shfl_sync(0xffffffffu, w, k);
            unsigned v = H[(size_t)sk * 32 + lane];
            ax += __uint_as_float(v << 16) * wk;
            ay += __uint_as_float(v & 0xffff0000u) * wk;
        }
    }

    int f0 = 2 * lane, f1 = 2 * lane + 1;
    bool v0 = f0 < FOUT, v1 = f1 < FOUT;
    if (v0) ax += b2[f0];
    if (v1) ay += b2[f1];

    float m = fmaxf(v0 ? ax : -INFINITY, v1 ? ay : -INFINITY);
#pragma unroll
    for (int off = 16; off; off >>= 1) m = fmaxf(m, __shfl_xor_sync(0xffffffffu, m, off));
    float e = (v0 ? expf(ax - m) : 0.f) + (v1 ? expf(ay - m) : 0.f);
#pragma unroll
    for (int off = 16; off; off >>= 1) e += __shfl_xor_sync(0xffffffffu, e, off);
    float ls = m + logf(e);
    if (v0) out[(size_t)i * FOUT + f0] = ax - ls;
    if (v1) out[(size_t)i * FOUT + f1] = ay - ls;
}

// ---------------- launch ----------------------------------------------------
extern "C" void kernel_launch(void* const* d_in, const int* in_sizes, int n_in,
                              void* d_out, int out_size)
{
    const float* x  = (const float*)d_in[0];
    const float* W1 = (const float*)d_in[1];
    const float* b1 = (const float*)d_in[2];
    const float* W2 = (const float*)d_in[3];
    const float* b2 = (const float*)d_in[4];
    const int*   ei = (const int*)d_in[5];   // int32 or int64; detected on device
    float* out = (float*)d_out;

    int n = in_sizes[0] / FIN;
    long long E = in_sizes[5] / 2;
    int nb = (n + 255) / 256;

    k_init<<<nb, 256>>>(ei, W2, n);
    k_degree<<<(int)((E + 255) / 256), 256>>>(ei, E);
    k_part<<<nb, 256>>>(n);
    k_write<<<nb, 256>>>(n, nb);
    k_scatter<<<(int)((E + 255) / 256), 256>>>(ei, E);
    k_gemm1<<<(n + 127) / 128, 256>>>(x, W1, n);
    k_agg1<<<(n * 32 + 255) / 256, 256>>>(b1, n);
    k_gemm2<<<(n + 63) / 64, 256>>>(n);
    k_agg2<<<(n * 32 + 255) / 256, 256>>>(b2, out, n);
}

// round 14
// speedup vs baseline: 4.0301x; 1.1534x over previous
#include <cuda_runtime.h>
#include <cuda_bf16.h>
#include <cuda_fp16.h>
#include <math.h>

// Problem constants (with headroom on N/E for safety)
#define FIN   500
#define FH    128
#define FOUT  47
#define NMAX  65536
#define EMAX  1048576

// ---------------- scratch (static device globals; no allocation) -------------
__device__ __align__(16) float g_dinv[NMAX];
__device__ int   g_cnt[NMAX];
__device__ int   g_rowptr[NMAX];
__device__ int   g_wp[NMAX];
__device__ int   g_col[EMAX];
__device__ int   g_total;
__device__ __align__(16) unsigned g_H1bf [(size_t)NMAX * 64];  // x @ W1, bf16x2
__device__ __align__(16) unsigned g_H1rbf[(size_t)NMAX * 64];  // relu(agg1+b1), bf16x2
__device__ __align__(16) unsigned g_H2bf [(size_t)NMAX * 32];  // H1r @ W2, bf16x2, 64-col pad
__device__ __align__(16) unsigned g_W2bf [128 * 32];           // W2 bf16x2, 64-col pad
__device__ int   g_is64;

__device__ __forceinline__ int ld_edge(const int* p, long long idx, int is64) {
    return is64 ? p[2 * idx] : p[idx];
}
__device__ __forceinline__ unsigned pack_bf16(float a, float b) {
    return ((unsigned)__bfloat16_as_ushort(__float2bfloat16(b)) << 16) |
           __bfloat16_as_ushort(__float2bfloat16(a));
}

// ---------------- init: zero counters + dtype detect + W2 pack ---------------
// int64 LE: odd 32-bit words are 0 (values < 50000). int32: odd words random.
__global__ void k_init(const int* ei, const float* W2, int n) {
    int i = blockIdx.x * blockDim.x + threadIdx.x;
    if (i < n) g_cnt[i] = 0;
    if (blockIdx.x == 0 && threadIdx.x < 32) {
        int lane = threadIdx.x;
        int nz = (ei[2 * lane + 1] != 0) ? 1 : 0;
        unsigned b = __ballot_sync(0xffffffffu, nz);
        if (lane == 0) { g_is64 = (b == 0u) ? 1 : 0; g_total = 0; }
    }
    if (blockIdx.x == 1) {
        for (int idx = threadIdx.x; idx < 128 * 32; idx += blockDim.x) {
            int k = idx >> 5, c2 = idx & 31;
            float f0 = (2 * c2     < FOUT) ? W2[k * FOUT + 2 * c2]     : 0.f;
            float f1 = (2 * c2 + 1 < FOUT) ? W2[k * FOUT + 2 * c2 + 1] : 0.f;
            g_W2bf[idx] = pack_bf16(f0, f1);
        }
    }
}

__global__ void k_degree(const int* ei, long long E) {
    long long e = (long long)blockIdx.x * blockDim.x + threadIdx.x;
    if (e >= E) return;
    int is64 = g_is64;
    int dst = ld_edge(ei, E + e, is64);
    atomicAdd(&g_cnt[dst], 1);
}

// ---------------- k_alloc: atomic chunk allocation (order-free CSR) ----------
// Block scans its 256 counts, grabs a base via one atomicAdd, writes
// rowptr (= row start), wp, dinv. Row order in g_col is arbitrary; each
// row is contiguous. Row length comes from g_cnt (preserved).
__global__ void k_alloc(int n) {
    __shared__ int sh[256];
    __shared__ int base_sh;
    int t = threadIdx.x;
    int i = blockIdx.x * 256 + t;
    int c = (i < n) ? g_cnt[i] : 0;
    sh[t] = c;
    __syncthreads();
#pragma unroll
    for (int off = 1; off < 256; off <<= 1) {
        int u = (t >= off) ? sh[t - off] : 0;
        __syncthreads();
        sh[t] += u;
        __syncthreads();
    }
    if (t == 0) base_sh = atomicAdd(&g_total, sh[255]);
    __syncthreads();
    if (i < n) {
        int pos = base_sh + sh[t] - c;
        g_rowptr[i] = pos;
        g_wp[i] = pos;
        g_dinv[i] = rsqrtf((float)(c + 1));   // +1 self-loop
    }
}

__global__ void k_scatter(const int* ei, long long E) {
    long long e = (long long)blockIdx.x * blockDim.x + threadIdx.x;
    if (e >= E) return;
    int is64 = g_is64;
    int src = ld_edge(ei, e, is64);
    int dst = ld_edge(ei, E + e, is64);
    int pos = atomicAdd(&g_wp[dst], 1);
    g_col[pos] = src;
}

// ---------------- mma helpers ------------------------------------------------
__device__ __forceinline__ void ldsm_x4(unsigned& r0, unsigned& r1, unsigned& r2, unsigned& r3,
                                        unsigned addr) {
    asm volatile("ldmatrix.sync.aligned.m8n8.x4.shared.b16 {%0,%1,%2,%3}, [%4];\n"
                 : "=r"(r0), "=r"(r1), "=r"(r2), "=r"(r3) : "r"(addr));
}
__device__ __forceinline__ void ldsm_x4_t(unsigned& r0, unsigned& r1, unsigned& r2, unsigned& r3,
                                          unsigned addr) {
    asm volatile("ldmatrix.sync.aligned.m8n8.x4.trans.shared.b16 {%0,%1,%2,%3}, [%4];\n"
                 : "=r"(r0), "=r"(r1), "=r"(r2), "=r"(r3) : "r"(addr));
}
__device__ __forceinline__ void mma_fp16(float* d, const unsigned* a, const unsigned* b) {
    asm volatile("mma.sync.aligned.m16n8k16.row.col.f32.f16.f16.f32 "
                 "{%0,%1,%2,%3}, {%4,%5,%6,%7}, {%8,%9}, {%0,%1,%2,%3};\n"
                 : "+f"(d[0]), "+f"(d[1]), "+f"(d[2]), "+f"(d[3])
                 : "r"(a[0]), "r"(a[1]), "r"(a[2]), "r"(a[3]), "r"(b[0]), "r"(b[1]));
}
__device__ __forceinline__ void mma_bf16(float* d, const unsigned* a, const unsigned* b) {
    asm volatile("mma.sync.aligned.m16n8k16.row.col.f32.bf16.bf16.f32 "
                 "{%0,%1,%2,%3}, {%4,%5,%6,%7}, {%8,%9}, {%0,%1,%2,%3};\n"
                 : "+f"(d[0]), "+f"(d[1]), "+f"(d[2]), "+f"(d[3])
                 : "r"(a[0]), "r"(a[1]), "r"(a[2]), "r"(a[3]), "r"(b[0]), "r"(b[1]));
}
// float4 -> 2x packed half2
__device__ __forceinline__ uint2 cvt4h(const float4 v) {
    __half2 h0 = __floats2half2_rn(v.x, v.y);
    __half2 h1 = __floats2half2_rn(v.z, v.w);
    uint2 r;
    r.x = *reinterpret_cast<unsigned*>(&h0);
    r.y = *reinterpret_cast<unsigned*>(&h1);
    return r;
}

// ---------------- GEMM1: H1 = x @ W1 via fp16 tensor cores -------------------
// 128x128 block tile, BK=16, K padded to 512 (32 chunks). 8 warps = 4m x 2n.
#define G1_KT 32
#define A_LDS 24
#define B_LDS 136
__global__ __launch_bounds__(256) void k_gemm1(
    const float* __restrict__ x, const float* __restrict__ W, int n)
{
    __shared__ __align__(16) __half As[2][128][A_LDS];
    __shared__ __align__(16) __half Bs[2][16][B_LDS];

    int tid = threadIdx.x;
    int lane = tid & 31;
    int wid = tid >> 5;
    int wm = wid & 3;
    int wn = wid >> 2;
    int row0 = blockIdx.x * 128;

    float acc[2][8][4];
#pragma unroll
    for (int mi = 0; mi < 2; mi++)
#pragma unroll
        for (int ni = 0; ni < 8; ni++)
#pragma unroll
            for (int q = 0; q < 4; q++) acc[mi][ni][q] = 0.f;

    unsigned a_base = (unsigned)__cvta_generic_to_shared(&As[0][0][0]);
    unsigned b_base = (unsigned)__cvta_generic_to_shared(&Bs[0][0][0]);
    const unsigned A_BUF = 128 * A_LDS * 2;
    const unsigned B_BUF = 16 * B_LDS * 2;
    unsigned a_lane = ((lane & 15) * A_LDS + (lane >> 4) * 8) * 2;
    unsigned b_lane = ((lane & 15) * B_LDS + (lane >> 4) * 8) * 2;

    float4 a_ld[2], b_ld[2];

#define G1_LOAD(k0)                                                            \
    {                                                                          \
        _Pragma("unroll")                                                      \
        for (int u = 0; u < 2; u++) {                                          \
            int f4 = tid + u * 256;                                            \
            int a_row = f4 >> 2, grp = f4 & 3;                                 \
            int gk = (k0) + grp * 4;                                           \
            int gr = row0 + a_row;                                             \
            if (gr < n && gk + 4 <= FIN)                                       \
                a_ld[u] = *reinterpret_cast<const float4*>(&x[(size_t)gr * FIN + gk]); \
            else a_ld[u] = make_float4(0.f, 0.f, 0.f, 0.f);                    \
            int bk = f4 >> 5, bc4 = f4 & 31;                                   \
            int gkb = (k0) + bk;                                               \
            if (gkb < FIN)                                                     \
                b_ld[u] = *reinterpret_cast<const float4*>(&W[(size_t)gkb * FH + bc4 * 4]); \
            else b_ld[u] = make_float4(0.f, 0.f, 0.f, 0.f);                    \
        }                                                                      \
    }

#define G1_STORE(buf)                                                          \
    {                                                                          \
        _Pragma("unroll")                                                      \
        for (int u = 0; u < 2; u++) {                                          \
            int f4 = tid + u * 256;                                            \
            int a_row = f4 >> 2, grp = f4 & 3;                                 \
            *reinterpret_cast<uint2*>(&As[buf][a_row][grp * 4]) = cvt4h(a_ld[u]); \
            int bk = f4 >> 5, bc4 = f4 & 31;                                   \
            *reinterpret_cast<uint2*>(&Bs[buf][bk][bc4 * 4]) = cvt4h(b_ld[u]); \
        }                                                                      \
    }

    G1_LOAD(0)
    G1_STORE(0)
    __syncthreads();

    for (int kt = 0; kt < G1_KT; kt++) {
        int cbuf = kt & 1;
        if (kt + 1 < G1_KT) G1_LOAD((kt + 1) * 16)

        unsigned af[2][4], bfr[8][2];
#pragma unroll
        for (int mi = 0; mi < 2; mi++) {
            unsigned roff = (unsigned)((wm * 32 + mi * 16) * A_LDS * 2);
            ldsm_x4(af[mi][0], af[mi][1], af[mi][2], af[mi][3],
                    a_base + cbuf * A_BUF + roff + a_lane);
        }
#pragma unroll
        for (int p = 0; p < 4; p++) {
            unsigned coff = (unsigned)((wn * 64 + p * 16) * 2);
            ldsm_x4_t(bfr[2*p][0], bfr[2*p][1], bfr[2*p+1][0], bfr[2*p+1][1],
                      b_base + cbuf * B_BUF + coff + b_lane);
        }

#pragma unroll
        for (int mi = 0; mi < 2; mi++)
#pragma unroll
            for (int ni = 0; ni < 8; ni++)
                mma_fp16(acc[mi][ni], af[mi], bfr[ni]);

        if (kt + 1 < G1_KT) G1_STORE(cbuf ^ 1)
        __syncthreads();
    }

    int rbase = row0 + wm * 32 + (lane >> 2);
    int cbase = wn * 64 + (lane & 3) * 2;
#pragma unroll
    for (int mi = 0; mi < 2; mi++) {
#pragma unroll
        for (int ni = 0; ni < 8; ni++) {
            int col = cbase + ni * 8;      // even
            int r0 = rbase + mi * 16;
            if (r0 < n)
                g_H1bf[(size_t)r0 * 64 + (col >> 1)] =
                    pack_bf16(acc[mi][ni][0], acc[mi][ni][1]);
            if (r0 + 8 < n)
                g_H1bf[(size_t)(r0 + 8) * 64 + (col >> 1)] =
                    pack_bf16(acc[mi][ni][2], acc[mi][ni][3]);
        }
    }
#undef G1_LOAD
#undef G1_STORE
}

// ---------------- agg1: H1r = relu( Ahat @ H1 + b1 ), bf16 out ---------------
__device__ __forceinline__ void bf2_fma(float4& acc, uint2 u, float w) {
    float f0 = __uint_as_float(u.x << 16);
    float f1 = __uint_as_float(u.x & 0xffff0000u);
    float f2 = __uint_as_float(u.y << 16);
    float f3 = __uint_as_float(u.y & 0xffff0000u);
    acc.x += f0 * w; acc.y += f1 * w; acc.z += f2 * w; acc.w += f3 * w;
}
__global__ __launch_bounds__(256) void k_agg1(const float* __restrict__ b1, int n) {
    int gw = (blockIdx.x * blockDim.x + threadIdx.x) >> 5;
    int lane = threadIdx.x & 31;
    if (gw >= n) return;
    int i = gw;
    float di = g_dinv[i];
    const uint2* H = reinterpret_cast<const uint2*>(g_H1bf);
    float4 acc = make_float4(0.f, 0.f, 0.f, 0.f);
    bf2_fma(acc, H[(size_t)i * 32 + lane], di * di);   // self loop

    int beg = g_rowptr[i], end = beg + g_cnt[i];
    for (int base = beg; base < end; base += 32) {
        int c = end - base; if (c > 32) c = 32;
        int s = 0; float w = 0.f;
        if (lane < c) { s = g_col[base + lane]; w = g_dinv[s] * di; }
        int k = 0;
        for (; k + 4 <= c; k += 4) {
            int   s0 = __shfl_sync(0xffffffffu, s, k);
            int   s1 = __shfl_sync(0xffffffffu, s, k + 1);
            int   s2 = __shfl_sync(0xffffffffu, s, k + 2);
            int   s3 = __shfl_sync(0xffffffffu, s, k + 3);
            float w0 = __shfl_sync(0xffffffffu, w, k);
            float w1 = __shfl_sync(0xffffffffu, w, k + 1);
            float w2 = __shfl_sync(0xffffffffu, w, k + 2);
            float w3 = __shfl_sync(0xffffffffu, w, k + 3);
            uint2 v0 = H[(size_t)s0 * 32 + lane];
            uint2 v1 = H[(size_t)s1 * 32 + lane];
            uint2 v2 = H[(size_t)s2 * 32 + lane];
            uint2 v3 = H[(size_t)s3 * 32 + lane];
            bf2_fma(acc, v0, w0);
            bf2_fma(acc, v1, w1);
            bf2_fma(acc, v2, w2);
            bf2_fma(acc, v3, w3);
        }
        for (; k < c; k++) {
            int   sk = __shfl_sync(0xffffffffu, s, k);
            float wk = __shfl_sync(0xffffffffu, w, k);
            bf2_fma(acc, H[(size_t)sk * 32 + lane], wk);
        }
    }
    float4 b = reinterpret_cast<const float4*>(b1)[lane];
    uint2 o;
    o.x = pack_bf16(fmaxf(acc.x + b.x, 0.f), fmaxf(acc.y + b.y, 0.f));
    o.y = pack_bf16(fmaxf(acc.z + b.z, 0.f), fmaxf(acc.w + b.w, 0.f));
    reinterpret_cast<uint2*>(g_H1rbf)[(size_t)i * 32 + lane] = o;
}

// ---------------- GEMM2: H2 = H1r @ W2 via bf16 tensor cores -----------------
// 64x64 block tile, K=128 resident in smem. 8 warps = 2m x 4n.
#define G2_ALD 136   // bf16 per A row (128 + 8 pad)
#define G2_BLD 72    // bf16 per B row (64 + 8 pad)
__global__ __launch_bounds__(256) void k_gemm2(int n) {
    __shared__ __align__(16) __nv_bfloat16 As[64][G2_ALD];
    __shared__ __align__(16) __nv_bfloat16 Bs[128][G2_BLD];

    int tid = threadIdx.x;
    int lane = tid & 31;
    int wid = tid >> 5;
    int wm = wid & 1;    // 2 warps along m, 32 rows each
    int wn = wid >> 1;   // 4 warps along n, 16 cols each
    int row0 = blockIdx.x * 64;

    const uint4* H1 = reinterpret_cast<const uint4*>(g_H1rbf);
#pragma unroll
    for (int u = 0; u < 4; u++) {
        int f = tid + u * 256;
        int r = f >> 4, seg = f & 15;
        int gr = row0 + r;
        uint4 v = make_uint4(0u, 0u, 0u, 0u);
        if (gr < n) v = H1[(size_t)gr * 16 + seg];
        *reinterpret_cast<uint4*>(&As[r][seg * 8]) = v;
    }
    const uint4* Wb = reinterpret_cast<const uint4*>(g_W2bf);
#pragma unroll
    for (int u = 0; u < 4; u++) {
        int f = tid + u * 256;
        int k = f >> 3, seg = f & 7;
        *reinterpret_cast<uint4*>(&Bs[k][seg * 8]) = Wb[f];
    }
    __syncthreads();

    float acc[2][2][4];
#pragma unroll
    for (int mi = 0; mi < 2; mi++)
#pragma unroll
        for (int ni = 0; ni < 2; ni++)
#pragma unroll
            for (int q = 0; q < 4; q++) acc[mi][ni][q] = 0.f;

    unsigned a_base = (unsigned)__cvta_generic_to_shared(&As[0][0]);
    unsigned b_base = (unsigned)__cvta_generic_to_shared(&Bs[0][0]);

#pragma unroll
    for (int k = 0; k < 8; k++) {
        unsigned af[2][4], bfr[2][2];
#pragma unroll
        for (int mi = 0; mi < 2; mi++) {
            unsigned addr = a_base +
                (unsigned)(((wm * 32 + mi * 16 + (lane & 15)) * G2_ALD +
                            k * 16 + (lane >> 4) * 8) * 2);
            ldsm_x4(af[mi][0], af[mi][1], af[mi][2], af[mi][3], addr);
        }
        unsigned baddr = b_base +
            (unsigned)(((k * 16 + (lane & 15)) * G2_BLD +
                        wn * 16 + (lane >> 4) * 8) * 2);
        ldsm_x4_t(bfr[0][0], bfr[0][1], bfr[1][0], bfr[1][1], baddr);
#pragma unroll
        for (int mi = 0; mi < 2; mi++)
#pragma unroll
            for (int ni = 0; ni < 2; ni++)
                mma_bf16(acc[mi][ni], af[mi], bfr[ni]);
    }

    int r_ = wm * 32 + (lane >> 2);
    int c0 = wn * 16 + (lane & 3) * 2;   // even
#pragma unroll
    for (int mi = 0; mi < 2; mi++) {
#pragma unroll
        for (int ni = 0; ni < 2; ni++) {
            int row = row0 + r_ + mi * 16;
            int col = c0 + ni * 8;
            if (row < n)
                g_H2bf[(size_t)row * 32 + (col >> 1)] =
                    pack_bf16(acc[mi][ni][0], acc[mi][ni][1]);
            if (row + 8 < n)
                g_H2bf[(size_t)(row + 8) * 32 + (col >> 1)] =
                    pack_bf16(acc[mi][ni][2], acc[mi][ni][3]);
        }
    }
}

// ---------------- agg2 + bias + log_softmax (bf16 gathers) -------------------
__global__ __launch_bounds__(256) void k_agg2(
    const float* __restrict__ b2, float* __restrict__ out, int n)
{
    int gw = (blockIdx.x * blockDim.x + threadIdx.x) >> 5;
    int lane = threadIdx.x & 31;
    if (gw >= n) return;
    int i = gw;
    float di = g_dinv[i];
    float sw = di * di;
    const unsigned* H = g_H2bf;
    unsigned u0 = H[(size_t)i * 32 + lane];
    float ax = __uint_as_float(u0 << 16) * sw;
    float ay = __uint_as_float(u0 & 0xffff0000u) * sw;

    int beg = g_rowptr[i], end = beg + g_cnt[i];
    for (int base = beg; base < end; base += 32) {
        int c = end - base; if (c > 32) c = 32;
        int s = 0; float w = 0.f;
        if (lane < c) { s = g_col[base + lane]; w = g_dinv[s] * di; }
        int k = 0;
        for (; k + 4 <= c; k += 4) {
            int   s0 = __shfl_sync(0xffffffffu, s, k);
            int   s1 = __shfl_sync(0xffffffffu, s, k + 1);
            int   s2 = __shfl_sync(0xffffffffu, s, k + 2);
            int   s3 = __shfl_sync(0xffffffffu, s, k + 3);
            float w0 = __shfl_sync(0xffffffffu, w, k);
            float w1 = __shfl_sync(0xffffffffu, w, k + 1);
            float w2 = __shfl_sync(0xffffffffu, w, k + 2);
            float w3 = __shfl_sync(0xffffffffu, w, k + 3);
            unsigned v0 = H[(size_t)s0 * 32 + lane];
            unsigned v1 = H[(size_t)s1 * 32 + lane];
            unsigned v2 = H[(size_t)s2 * 32 + lane];
            unsigned v3 = H[(size_t)s3 * 32 + lane];
            ax += __uint_as_float(v0 << 16) * w0; ay += __uint_as_float(v0 & 0xffff0000u) * w0;
            ax += __uint_as_float(v1 << 16) * w1; ay += __uint_as_float(v1 & 0xffff0000u) * w1;
            ax += __uint_as_float(v2 << 16) * w2; ay += __uint_as_float(v2 & 0xffff0000u) * w2;
            ax += __uint_as_float(v3 << 16) * w3; ay += __uint_as_float(v3 & 0xffff0000u) * w3;
        }
        for (; k < c; k++) {
            int   sk = __shfl_sync(0xffffffffu, s, k);
            float wk = __shfl_sync(0xffffffffu, w, k);
            unsigned v = H[(size_t)sk * 32 + lane];
            ax += __uint_as_float(v << 16) * wk;
            ay += __uint_as_float(v & 0xffff0000u) * wk;
        }
    }

    int f0 = 2 * lane, f1 = 2 * lane + 1;
    bool v0 = f0 < FOUT, v1 = f1 < FOUT;
    if (v0) ax += b2[f0];
    if (v1) ay += b2[f1];

    float m = fmaxf(v0 ? ax : -INFINITY, v1 ? ay : -INFINITY);
#pragma unroll
    for (int off = 16; off; off >>= 1) m = fmaxf(m, __shfl_xor_sync(0xffffffffu, m, off));
    float e = (v0 ? expf(ax - m) : 0.f) + (v1 ? expf(ay - m) : 0.f);
#pragma unroll
    for (int off = 16; off; off >>= 1) e += __shfl_xor_sync(0xffffffffu, e, off);
    float ls = m + logf(e);
    if (v0) out[(size_t)i * FOUT + f0] = ax - ls;
    if (v1) out[(size_t)i * FOUT + f1] = ay - ls;
}

// ---------------- launch ----------------------------------------------------
// CSR build (stream 0) runs concurrently with gemm1 (stream s1); they touch
// disjoint buffers. Fork/join via events so the dependency is captured in the
// graph. Stream/event handles are host-side resources created once (no device
// allocation, no behavior change across calls).
extern "C" void kernel_launch(void* const* d_in, const int* in_sizes, int n_in,
                              void* d_out, int out_size)
{
    const float* x  = (const float*)d_in[0];
    const float* W1 = (const float*)d_in[1];
    const float* b1 = (const float*)d_in[2];
    const float* W2 = (const float*)d_in[3];
    const float* b2 = (const float*)d_in[4];
    const int*   ei = (const int*)d_in[5];   // int32 or int64; detected on device
    float* out = (float*)d_out;

    int n = in_sizes[0] / FIN;
    long long E = in_sizes[5] / 2;
    int nb = (n + 255) / 256;

    static cudaStream_t s1 = nullptr;
    static cudaEvent_t eFork = nullptr, eJoin = nullptr;
    if (s1 == nullptr) {
        cudaStreamCreateWithFlags(&s1, cudaStreamNonBlocking);
        cudaEventCreateWithFlags(&eFork, cudaEventDisableTiming);
        cudaEventCreateWithFlags(&eJoin, cudaEventDisableTiming);
    }

    // fork: gemm1 on s1, independent of the CSR build
    cudaEventRecord(eFork, 0);
    cudaStreamWaitEvent(s1, eFork, 0);
    k_gemm1<<<(n + 127) / 128, 256, 0, s1>>>(x, W1, n);
    cudaEventRecord(eJoin, s1);

    // CSR build on stream 0
    k_init<<<nb, 256>>>(ei, W2, n);
    k_degree<<<(int)((E + 255) / 256), 256>>>(ei, E);
    k_alloc<<<nb, 256>>>(n);
    k_scatter<<<(int)((E + 255) / 256), 256>>>(ei, E);

    // join: agg1 needs both CSR and H1
    cudaStreamWaitEvent(0, eJoin, 0);
    k_agg1<<<(n * 32 + 255) / 256, 256>>>(b1, n);
    k_gemm2<<<(n + 63) / 64, 256>>>(n);
    k_agg2<<<(n * 32 + 255) / 256, 256>>>(b2, out, n);
}